// round 8
// baseline (speedup 1.0000x reference)
#include <cuda_runtime.h>
#include <math.h>
#include <stdint.h>

#define NN 100000
#define EE 1200000
#define BB 64
#define NSTEPS 6
#define GRID 1563   // ceil(NN/64)

__device__ float g_h[NN * 64];
__device__ float g_h0[NN * 64];
__device__ float g_a[NN * 64];
__device__ int   g_rowstart[NN + 1];
__device__ int   g_cursor[NN];
__device__ int   g_eidx[EE];
__device__ int   g_cnt4[NN * 4];      // static-init zero; re-zeroed by tail kernel
__device__ float g_gate[NN];
__device__ float g_gmax[BB];          // 0.0 initially: mathematically equivalent guard
__device__ float g_den[BB];
__device__ float g_rsum[BB * 128];

__device__ __forceinline__ float tf32r(float x){ float y; asm("cvt.rna.tf32.f32 %0,%1;":"=f"(y):"f"(x)); return y; }

// fragment-permuted indices (m16n8k8 tf32 mma.sync layouts), kcs = K/8 chunks
__device__ __forceinline__ int aidx(int row,int k,int kcs){
    int mt=row>>4, r=row&15;
    return (((mt*kcs+(k>>3))<<5) + (((r&7)<<2)+(k&3)))*4 + ((r>>3)+(((k>>2)&1)<<1));
}
__device__ __forceinline__ int bidx(int k,int n,int kcs){
    return ((((n>>3)*kcs+(k>>3))<<5) + (((n&7)<<2)+(k&3)))*2 + ((k>>2)&1);
}
__device__ __forceinline__ void mma8(float* c,const uint32_t* a,const uint32_t* b){
    asm volatile("mma.sync.aligned.m16n8k8.row.col.f32.tf32.tf32.f32 "
        "{%0,%1,%2,%3},{%4,%5,%6,%7},{%8,%9},{%0,%1,%2,%3};"
        : "+f"(c[0]),"+f"(c[1]),"+f"(c[2]),"+f"(c[3])
        : "r"(a[0]),"r"(a[1]),"r"(a[2]),"r"(a[3]),"r"(b[0]),"r"(b[1]));
}
__device__ __forceinline__ void splitA4(float4 v,uint32_t* ah,uint32_t* al){
    float h;
    h=tf32r(v.x); ah[0]=__float_as_uint(h); al[0]=__float_as_uint(tf32r(v.x-h));
    h=tf32r(v.y); ah[1]=__float_as_uint(h); al[1]=__float_as_uint(tf32r(v.y-h));
    h=tf32r(v.z); ah[2]=__float_as_uint(h); al[2]=__float_as_uint(tf32r(v.z-h));
    h=tf32r(v.w); ah[3]=__float_as_uint(h); al[3]=__float_as_uint(tf32r(v.w-h));
}
__device__ __forceinline__ void splitB2(float2 v,uint32_t* bh,uint32_t* bl){
    float h;
    h=tf32r(v.x); bh[0]=__float_as_uint(h); bl[0]=__float_as_uint(tf32r(v.x-h));
    h=tf32r(v.y); bh[1]=__float_as_uint(h); bl[1]=__float_as_uint(tf32r(v.y-h));
}

// smem layout (floats): A fp32 perm [0,8192) | B fp32 perm [8192,16384)
#define OB 8192
#define SMB (16384*4)

// ---------------- CSR build ----------------------------------------------------
__global__ void hist_kernel(const int* __restrict__ dst,const int* __restrict__ ety){
    int e=blockIdx.x*blockDim.x+threadIdx.x; if(e<EE) atomicAdd(&g_cnt4[dst[e]*4+ety[e]],1);
}
__global__ void scan_kernel(){
    __shared__ int part[1024];
    int tid=threadIdx.x; const int CH=(NN+1023)/1024; int base=tid*CH; int s=0;
    for(int i=0;i<CH;++i){ int n=base+i; if(n<NN) s+=g_cnt4[n*4]+g_cnt4[n*4+1]+g_cnt4[n*4+2]+g_cnt4[n*4+3]; }
    part[tid]=s; __syncthreads();
    for(int off=1;off<1024;off<<=1){ int v=(tid>=off)?part[tid-off]:0; __syncthreads(); part[tid]+=v; __syncthreads(); }
    int run=(tid?part[tid-1]:0);
    for(int i=0;i<CH;++i){ int n=base+i; if(n<NN){ g_rowstart[n]=run; g_cursor[n]=run;
        run+=g_cnt4[n*4]+g_cnt4[n*4+1]+g_cnt4[n*4+2]+g_cnt4[n*4+3]; } }
    if(tid==1023) g_rowstart[NN]=part[1023];
}
__global__ void fill_kernel(const int* __restrict__ src,const int* __restrict__ dst,const int* __restrict__ ety){
    int e=blockIdx.x*blockDim.x+threadIdx.x;
    if(e<EE){ int pos=atomicAdd(&g_cursor[dst[e]],1); g_eidx[pos]=(src[e]<<2)|ety[e]; }
}

// ---------------- reduce: h0 = ann @ reduce_W + rb (3xTF32, reg-split) ----------
__global__ __launch_bounds__(512,2) void reduce_mma(const float* __restrict__ ann,
        const float* __restrict__ rW,const float* __restrict__ rb){
    extern __shared__ float smf[];
    const int tid=threadIdx.x,w=tid>>5,lane=tid&31; const int n0=blockIdx.x*64;
    const int mtile=w>>2,nt0=(w&3)*2;
    float C[2][4]={};
    for(int st=0;st<2;++st){
        for(int idx=tid;idx<2048;idx+=512){
            int row=idx>>5,k=(idx&31)<<2; int n=n0+row;
            float4 v=make_float4(0,0,0,0);
            if(n<NN) v=*(const float4*)&ann[(size_t)n*256+st*128+k];
            smf[aidx(row,k+0,16)]=v.x; smf[aidx(row,k+1,16)]=v.y;
            smf[aidx(row,k+2,16)]=v.z; smf[aidx(row,k+3,16)]=v.w;
        }
        for(int idx=tid;idx<8192;idx+=512){
            int k=idx>>6,nc=idx&63;
            smf[OB+bidx(k,nc,16)]=rW[(size_t)(st*128+k)*64+nc];
        }
        __syncthreads();
        for(int kc=0;kc<16;++kc){
            float4 af=*(const float4*)&smf[((mtile*16+kc)*32+lane)*4];
            uint32_t ah[4],al[4]; splitA4(af,ah,al);
#pragma unroll
            for(int j=0;j<2;++j){
                float2 bf=*(const float2*)&smf[OB+(((nt0+j)*16+kc)*32+lane)*2];
                uint32_t bh[2],bl[2]; splitB2(bf,bh,bl);
                mma8(C[j],ah,bh); mma8(C[j],ah,bl); mma8(C[j],al,bh);
            }
        }
        __syncthreads();
    }
    const int g=lane>>2,tig=lane&3;
    int r0=n0+mtile*16+g, r1=r0+8;
#pragma unroll
    for(int j=0;j<2;++j){
        int cb=(nt0+j)*8+2*tig;
        float b0=rb[cb],b1=rb[cb+1];
        if(r0<NN){ float2 v={C[j][0]+b0,C[j][1]+b1};
            *(float2*)&g_h0[(size_t)r0*64+cb]=v; *(float2*)&g_h[(size_t)r0*64+cb]=v; }
        if(r1<NN){ float2 v={C[j][2]+b0,C[j][3]+b1};
            *(float2*)&g_h0[(size_t)r1*64+cb]=v; *(float2*)&g_h[(size_t)r1*64+cb]=v; }
    }
}

// ---------------- agg: a = per-type CSR sums @ edge_W + cnt*edge_b --------------
__global__ __launch_bounds__(512,2) void agg_mma(const float* __restrict__ eW,
        const float* __restrict__ eb){
    extern __shared__ float smf[];
    const int tid=threadIdx.x,w=tid>>5,lane=tid&31; const int n0=blockIdx.x*64;
    float2 st2[4],st3[4];
    for(int i=0;i<4;++i){
        int nloc=w*4+i, n=n0+nloc;
        float2 a0={0,0},a1={0,0},a2={0,0},a3={0,0};
        if(n<NN){
            int e=g_rowstart[n],re=g_rowstart[n+1];
            for(;e+4<=re;e+=4){
                int v0=g_eidx[e],v1=g_eidx[e+1],v2=g_eidx[e+2],v3=g_eidx[e+3];
                float2 x0=*(const float2*)&g_h[(size_t)(v0>>2)*64+(lane<<1)];
                float2 x1=*(const float2*)&g_h[(size_t)(v1>>2)*64+(lane<<1)];
                float2 x2=*(const float2*)&g_h[(size_t)(v2>>2)*64+(lane<<1)];
                float2 x3=*(const float2*)&g_h[(size_t)(v3>>2)*64+(lane<<1)];
                int t0=v0&3,t1=v1&3,t2=v2&3,t3=v3&3;
                if(t0==0){a0.x+=x0.x;a0.y+=x0.y;}else if(t0==1){a1.x+=x0.x;a1.y+=x0.y;}
                else if(t0==2){a2.x+=x0.x;a2.y+=x0.y;}else{a3.x+=x0.x;a3.y+=x0.y;}
                if(t1==0){a0.x+=x1.x;a0.y+=x1.y;}else if(t1==1){a1.x+=x1.x;a1.y+=x1.y;}
                else if(t1==2){a2.x+=x1.x;a2.y+=x1.y;}else{a3.x+=x1.x;a3.y+=x1.y;}
                if(t2==0){a0.x+=x2.x;a0.y+=x2.y;}else if(t2==1){a1.x+=x2.x;a1.y+=x2.y;}
                else if(t2==2){a2.x+=x2.x;a2.y+=x2.y;}else{a3.x+=x2.x;a3.y+=x2.y;}
                if(t3==0){a0.x+=x3.x;a0.y+=x3.y;}else if(t3==1){a1.x+=x3.x;a1.y+=x3.y;}
                else if(t3==2){a2.x+=x3.x;a2.y+=x3.y;}else{a3.x+=x3.x;a3.y+=x3.y;}
            }
            for(;e<re;++e){
                int v=g_eidx[e]; float2 x=*(const float2*)&g_h[(size_t)(v>>2)*64+(lane<<1)]; int t=v&3;
                if(t==0){a0.x+=x.x;a0.y+=x.y;}else if(t==1){a1.x+=x.x;a1.y+=x.y;}
                else if(t==2){a2.x+=x.x;a2.y+=x.y;}else{a3.x+=x.x;a3.y+=x.y;}
            }
        }
        int k=lane<<1;
        smf[aidx(nloc,k,16)]=a0.x;      smf[aidx(nloc,k+1,16)]=a0.y;
        smf[aidx(nloc,64+k,16)]=a1.x;   smf[aidx(nloc,64+k+1,16)]=a1.y;
        st2[i]=a2; st3[i]=a3;
    }
    const int mtile=w>>2,nt0=(w&3)*2;
    float C[2][4]={};
    for(int st=0;st<2;++st){
        if(st==1){
            for(int i=0;i<4;++i){
                int nloc=w*4+i,k=lane<<1;
                smf[aidx(nloc,k,16)]=st2[i].x;    smf[aidx(nloc,k+1,16)]=st2[i].y;
                smf[aidx(nloc,64+k,16)]=st3[i].x; smf[aidx(nloc,64+k+1,16)]=st3[i].y;
            }
        }
        for(int idx=tid;idx<8192;idx+=512){
            int k=idx>>6,nc=idx&63; int kg=st*128+k;
            smf[OB+bidx(k,nc,16)]=eW[(size_t)(kg>>6)*4096+(kg&63)*64+nc];
        }
        __syncthreads();
        for(int kc=0;kc<16;++kc){
            float4 af=*(const float4*)&smf[((mtile*16+kc)*32+lane)*4];
            uint32_t ah[4],al[4]; splitA4(af,ah,al);
#pragma unroll
            for(int j=0;j<2;++j){
                float2 bf=*(const float2*)&smf[OB+(((nt0+j)*16+kc)*32+lane)*2];
                uint32_t bh[2],bl[2]; splitB2(bf,bh,bl);
                mma8(C[j],ah,bh); mma8(C[j],ah,bl); mma8(C[j],al,bh);
            }
        }
        __syncthreads();
    }
    const int g=lane>>2,tig=lane&3;
    int r0=n0+mtile*16+g, r1=r0+8;
#pragma unroll
    for(int j=0;j<2;++j){
        int cb=(nt0+j)*8+2*tig;
        float e00=eb[cb],e01=eb[cb+1],e10=eb[64+cb],e11=eb[64+cb+1];
        float e20=eb[128+cb],e21=eb[128+cb+1],e30=eb[192+cb],e31=eb[192+cb+1];
        if(r0<NN){ int4 c=*(const int4*)&g_cnt4[r0*4];
            float2 v={C[j][0]+c.x*e00+c.y*e10+c.z*e20+c.w*e30,
                      C[j][1]+c.x*e01+c.y*e11+c.z*e21+c.w*e31};
            *(float2*)&g_a[(size_t)r0*64+cb]=v; }
        if(r1<NN){ int4 c=*(const int4*)&g_cnt4[r1*4];
            float2 v={C[j][2]+c.x*e00+c.y*e10+c.z*e20+c.w*e30,
                      C[j][3]+c.x*e01+c.y*e11+c.z*e21+c.w*e31};
            *(float2*)&g_a[(size_t)r1*64+cb]=v; }
    }
}

// ---------------- fused GRU: gates r, hn, z, in staged sequentially -------------
__global__ __launch_bounds__(512,2) void gru_mma(const float* __restrict__ Wi,
        const float* __restrict__ Wh,const float* __restrict__ bi,const float* __restrict__ bh_){
    extern __shared__ float smf[];
    const int tid=threadIdx.x,w=tid>>5,lane=tid&31; const int n0=blockIdx.x*64;
    const int mtile=w>>2,nt0=(w&3)*2;
    // A = [a|h] K=128, resident
    for(int idx=tid;idx<2048;idx+=512){
        int row=idx>>5,k=(idx&31)<<2; int n=n0+row;
        float4 v=make_float4(0,0,0,0);
        if(n<NN) v=(k<64)?*(const float4*)&g_a[(size_t)n*64+k]:*(const float4*)&g_h[(size_t)n*64+k-64];
        smf[aidx(row,k+0,16)]=v.x; smf[aidx(row,k+1,16)]=v.y;
        smf[aidx(row,k+2,16)]=v.z; smf[aidx(row,k+3,16)]=v.w;
    }
    const int g=lane>>2,tig=lane&3;
    const int r0=n0+mtile*16+g, r1=r0+8;
    const int cb[2]={(nt0+0)*8+2*tig,(nt0+1)*8+2*tig};
    float tt[2][4], zv[2][4];

#define MMA_GATE(C,KC0,KC1)                                                     \
    for(int kc=(KC0);kc<(KC1);++kc){                                            \
        float4 af=*(const float4*)&smf[((mtile*16+kc)*32+lane)*4];              \
        uint32_t ah[4],al[4]; splitA4(af,ah,al);                                \
        _Pragma("unroll")                                                       \
        for(int j=0;j<2;++j){                                                   \
            float2 bf=*(const float2*)&smf[OB+(((nt0+j)*16+kc)*32+lane)*2];     \
            uint32_t bhv[2],blv[2]; splitB2(bf,bhv,blv);                        \
            mma8(C[j],ah,bhv); mma8(C[j],ah,blv); mma8(C[j],al,bhv);            \
        }                                                                       \
    }

    // ---- gate r (K=128) ----
    for(int idx=tid;idx<8192;idx+=512){ int k=idx>>6,nc=idx&63;
        smf[OB+bidx(k,nc,16)]=(k<64)?Wi[nc*64+k]:Wh[nc*64+(k-64)]; }
    __syncthreads();
    float rv[2][4];
    { float C[2][4]={}; MMA_GATE(C,0,16)
#pragma unroll
      for(int j=0;j<2;++j)
#pragma unroll
        for(int i=0;i<4;++i){ int col=cb[j]+(i&1);
            rv[j][i]=1.f/(1.f+expf(-(C[j][i]+bi[col]+bh_[col]))); } }
    __syncthreads();

    // ---- gate hn (K=64, h half: kc 8..15) ----
    for(int idx=tid;idx<4096;idx+=512){ int k=64+(idx>>6),nc=idx&63;
        smf[OB+bidx(k,nc,16)]=Wh[(size_t)(128+nc)*64+(k-64)]; }
    __syncthreads();
    { float C[2][4]={}; MMA_GATE(C,8,16)
#pragma unroll
      for(int j=0;j<2;++j)
#pragma unroll
        for(int i=0;i<4;++i){ int col=cb[j]+(i&1);
            tt[j][i]=rv[j][i]*(C[j][i]+bh_[128+col]); } }
    __syncthreads();

    // ---- gate z (K=128) ----
    for(int idx=tid;idx<8192;idx+=512){ int k=idx>>6,nc=idx&63;
        smf[OB+bidx(k,nc,16)]=(k<64)?Wi[(size_t)(64+nc)*64+k]:Wh[(size_t)(64+nc)*64+(k-64)]; }
    __syncthreads();
    { float C[2][4]={}; MMA_GATE(C,0,16)
#pragma unroll
      for(int j=0;j<2;++j)
#pragma unroll
        for(int i=0;i<4;++i){ int col=cb[j]+(i&1);
            zv[j][i]=1.f/(1.f+expf(-(C[j][i]+bi[64+col]+bh_[64+col]))); } }
    __syncthreads();

    // ---- gate in (K=64, a half: kc 0..7) + epilogue ----
    for(int idx=tid;idx<4096;idx+=512){ int k=idx>>6,nc=idx&63;
        smf[OB+bidx(k,nc,16)]=Wi[(size_t)(128+nc)*64+k]; }
    __syncthreads();
    { float C[2][4]={}; MMA_GATE(C,0,8)
#pragma unroll
      for(int j=0;j<2;++j)
#pragma unroll
        for(int i=0;i<4;++i){
            int col=cb[j]+(i&1); int row=(i<2)?r0:r1;
            if(row<NN){
                float nv=tanhf(C[j][i]+bi[128+col]+tt[j][i]);
                float ho=g_h[(size_t)row*64+col];
                g_h[(size_t)row*64+col]=(1.f-zv[j][i])*nv+zv[j][i]*ho;
            } } }
#undef MMA_GATE
}

// ---------------- attention pooling ----------------------------------------------
__device__ void atomicMaxFloat(float* addr,float v){
    int* ia=(int*)addr; int old=*ia;
    while(true){ float f=__int_as_float(old); if(f>=v) break;
        int as=old; old=atomicCAS(ia,as,__float_as_int(v)); if(old==as) break; }
}
__global__ __launch_bounds__(256) void gate_kernel(const int* __restrict__ gid,
        const float* __restrict__ gW,const float* __restrict__ gb){
    int gt=blockIdx.x*blockDim.x+threadIdx.x; int n=gt>>5; if(n>=NN) return;
    int lane=gt&31,j0=lane<<2;
    float4 fv=(j0<64)?*(const float4*)&g_h[(size_t)n*64+j0]:*(const float4*)&g_h0[(size_t)n*64+j0-64];
    float4 wv=*(const float4*)&gW[j0];
    float s=fv.x*wv.x+fv.y*wv.y+fv.z*wv.z+fv.w*wv.w;
#pragma unroll
    for(int o=16;o;o>>=1) s+=__shfl_xor_sync(0xffffffffu,s,o);
    if(lane==0){ float g=s+gb[0]; g_gate[n]=g; atomicMaxFloat(&g_gmax[gid[n]],g); }
}
__global__ __launch_bounds__(256) void pool_kernel(const int* __restrict__ gid){
    int gt=blockIdx.x*blockDim.x+threadIdx.x; int n=gt>>5; if(n>=NN) return;
    int lane=gt&31; int g=gid[n];
    float gm=g_gmax[g]; if(!isfinite(gm)) gm=0.f;
    float e=expf(g_gate[n]-gm);
    int j0=lane<<2;
    float4 fv=(j0<64)?*(const float4*)&g_h[(size_t)n*64+j0]:*(const float4*)&g_h0[(size_t)n*64+j0-64];
    float* rp=&g_rsum[g*128+j0];
    atomicAdd(rp,e*fv.x); atomicAdd(rp+1,e*fv.y); atomicAdd(rp+2,e*fv.z); atomicAdd(rp+3,e*fv.w);
    if(lane==0) atomicAdd(&g_den[g],e);
}
__global__ void out_kernel(const float* __restrict__ oW,const float* __restrict__ ob,float* __restrict__ out){
    int b=blockIdx.x,tid=threadIdx.x;
    float dn=g_den[b]; float inv=(dn>0.f)?(1.f/dn):0.f;
    float r=g_rsum[b*128+tid]*inv;
    float p0=r*oW[tid*2],p1=r*oW[tid*2+1];
#pragma unroll
    for(int o=16;o;o>>=1){ p0+=__shfl_xor_sync(0xffffffffu,p0,o); p1+=__shfl_xor_sync(0xffffffffu,p1,o); }
    __shared__ float s0[4],s1[4];
    if((tid&31)==0){ s0[tid>>5]=p0; s1[tid>>5]=p1; }
    __syncthreads();
    if(tid==0){ out[b*2]=s0[0]+s0[1]+s0[2]+s0[3]+ob[0]; out[b*2+1]=s1[0]+s1[1]+s1[2]+s1[3]+ob[1]; }
}
// reset state for the next (graph-replayed) call
__global__ void tail_zero(){
    int i=blockIdx.x*blockDim.x+threadIdx.x;
    if(i<NN*4) g_cnt4[i]=0;
    if(i<BB*128) g_rsum[i]=0.f;
    if(i<BB){ g_den[i]=0.f; g_gmax[i]=__int_as_float(0xff800000); }
}

// ---------------- host orchestration ---------------------------------------------
extern "C" void kernel_launch(void* const* d_in,const int* in_sizes,int n_in,
                              void* d_out,int out_size){
    const float* ann=(const float*)d_in[0];
    const int* src=(const int*)d_in[1];
    const int* dst=(const int*)d_in[2];
    const int* ety=(const int*)d_in[3];
    const int* gid=(const int*)d_in[4];
    const float* reduce_W=(const float*)d_in[5];
    const float* reduce_b=(const float*)d_in[6];
    const float* edge_W=(const float*)d_in[7];
    const float* edge_b=(const float*)d_in[8];
    const float* gru_Wi=(const float*)d_in[9];
    const float* gru_bi=(const float*)d_in[10];
    const float* gru_Wh=(const float*)d_in[11];
    const float* gru_bh=(const float*)d_in[12];
    const float* gate_W=(const float*)d_in[13];
    const float* gate_b=(const float*)d_in[14];
    const float* out_W=(const float*)d_in[15];
    const float* out_b=(const float*)d_in[16];
    float* out=(float*)d_out;

    cudaFuncSetAttribute(reduce_mma,cudaFuncAttributeMaxDynamicSharedMemorySize,SMB);
    cudaFuncSetAttribute(agg_mma,cudaFuncAttributeMaxDynamicSharedMemorySize,SMB);
    cudaFuncSetAttribute(gru_mma,cudaFuncAttributeMaxDynamicSharedMemorySize,SMB);

    // harness adds 2 launches; ncu -s 5 -c 1 profiles OUR launch #4 = reduce_mma
    hist_kernel<<<(EE+255)/256,256>>>(dst,ety);                        // 1
    scan_kernel<<<1,1024>>>();                                         // 2
    fill_kernel<<<(EE+255)/256,256>>>(src,dst,ety);                    // 3
    reduce_mma<<<GRID,512,SMB>>>(ann,reduce_W,reduce_b);               // 4 <- profiled
    for(int s=0;s<NSTEPS;++s){
        agg_mma<<<GRID,512,SMB>>>(edge_W,edge_b);
        gru_mma<<<GRID,512,SMB>>>(gru_Wi,gru_Wh,gru_bi,gru_bh);
    }
    gate_kernel<<<(NN*32+255)/256,256>>>(gid,gate_W,gate_b);
    pool_kernel<<<(NN*32+255)/256,256>>>(gid);
    out_kernel<<<BB,128>>>(out_W,out_b,out);
    tail_zero<<<(NN*4+255)/256,256>>>();
}

// round 9
// speedup vs baseline: 1.1125x; 1.1125x over previous
#include <cuda_runtime.h>
#include <math.h>
#include <stdint.h>

#define NN 100000
#define EE 1200000
#define BB 64
#define NSTEPS 6
#define GRID 3125   // NN/32

__device__ float g_h[NN * 64];
__device__ float g_h0[NN * 64];
__device__ float g_a[NN * 64];
__device__ int   g_rowstart[NN + 1];
__device__ int   g_cursor[NN];
__device__ int   g_eidx[EE];
__device__ int   g_cnt4[NN * 4];
__device__ float g_gate[NN];
__device__ float g_gmax[BB];
__device__ float g_den[BB];
__device__ float g_rsum[BB * 128];
// pre-split, fragment-permuted B tiles (packed once per launch)
__device__ float g_BredH[16384],g_BredL[16384];   // 2 stages K=128
__device__ float g_BedgeH[16384],g_BedgeL[16384]; // 2 stages K=128
__device__ float g_BrH[8192],g_BrL[8192];         // K=128
__device__ float g_BzH[8192],g_BzL[8192];         // K=128
__device__ float g_BinH[4096],g_BinL[4096];       // K=64
__device__ float g_BhnH[4096],g_BhnL[4096];       // K=64

__device__ __forceinline__ float tf32r(float x){ float y; asm("cvt.rna.tf32.f32 %0,%1;":"=f"(y):"f"(x)); return y; }

// fragment-permuted indices (m16n8k8 tf32), kcs = K/8
__device__ __forceinline__ int aidx(int row,int k,int kcs){
    int mt=row>>4, r=row&15;
    return (((mt*kcs+(k>>3))<<5) + (((r&7)<<2)+(k&3)))*4 + ((r>>3)+(((k>>2)&1)<<1));
}
__device__ __forceinline__ int bidx(int k,int n,int kcs){
    return ((((n>>3)*kcs+(k>>3))<<5) + (((n&7)<<2)+(k&3)))*2 + ((k>>2)&1);
}
__device__ __forceinline__ void mma8(float* c,const uint32_t* a,const uint32_t* b){
    asm volatile("mma.sync.aligned.m16n8k8.row.col.f32.tf32.tf32.f32 "
        "{%0,%1,%2,%3},{%4,%5,%6,%7},{%8,%9},{%0,%1,%2,%3};"
        : "+f"(c[0]),"+f"(c[1]),"+f"(c[2]),"+f"(c[3])
        : "r"(a[0]),"r"(a[1]),"r"(a[2]),"r"(a[3]),"r"(b[0]),"r"(b[1]));
}

// smem (floats): Ah[0,4096) Al[4096,8192) Bh[8192,16384) Bl[16384,24576)
#define OAL 4096
#define OBH 8192
#define OBL 16384
#define SMB (24576*4)

// splits v, stores hi/lo into pre-split A smem
__device__ __forceinline__ void stA(float* smf,int row,int k,float v){
    float h=tf32r(v);
    smf[aidx(row,k,16)]=h; smf[OAL+aidx(row,k,16)]=tf32r(v-h);
}
__device__ __forceinline__ void fillB(float* smf,const float* BH,const float* BL,int nf4,int tid){
    for(int i=tid;i<nf4;i+=512){
        ((float4*)(smf+OBH))[i]=((const float4*)BH)[i];
        ((float4*)(smf+OBL))[i]=((const float4*)BL)[i];
    }
}
// 3 mma for one (kc) step: A from pre-split smem, B from pre-split smem
__device__ __forceinline__ void mmastep(float* C,const float* smf,int akc,int bkc,int nt,int lane){
    uint4 ah=*(const uint4*)&smf[(akc*32+lane)*4];
    uint4 al=*(const uint4*)&smf[OAL+(akc*32+lane)*4];
    uint2 bh=*(const uint2*)&smf[OBH+(bkc*32+lane)*2];
    uint2 bl=*(const uint2*)&smf[OBL+(bkc*32+lane)*2];
    mma8(C,(const uint32_t*)&ah,(const uint32_t*)&bh);
    mma8(C,(const uint32_t*)&ah,(const uint32_t*)&bl);
    mma8(C,(const uint32_t*)&al,(const uint32_t*)&bh);
}

// ---------------- prep: histogram + weight pre-split/permute ---------------------
__global__ void prep_kernel(const int* __restrict__ dst,const int* __restrict__ ety,
        const float* __restrict__ rW,const float* __restrict__ eW,
        const float* __restrict__ Wi,const float* __restrict__ Wh){
    int i=blockIdx.x*blockDim.x+threadIdx.x;
    if(i<EE) atomicAdd(&g_cnt4[dst[i]*4+ety[i]],1);
    if(i<16384){ int k=i>>6,n=i&63; float v=rW[k*64+n];
        int off=(k>>7)*8192+bidx(k&127,n,16);
        float h=tf32r(v); g_BredH[off]=h; g_BredL[off]=tf32r(v-h);
    }else if(i<32768){ int q=i-16384; int k=q>>6,n=q&63;
        float v=eW[(k>>6)*4096+(k&63)*64+n];
        int off=(k>>7)*8192+bidx(k&127,n,16);
        float h=tf32r(v); g_BedgeH[off]=h; g_BedgeL[off]=tf32r(v-h);
    }else if(i<40960){ int q=i-32768; int k=q>>6,n=q&63;
        float v=(k<64)?Wi[n*64+k]:Wh[n*64+k-64];
        int off=bidx(k,n,16);
        float h=tf32r(v); g_BrH[off]=h; g_BrL[off]=tf32r(v-h);
    }else if(i<49152){ int q=i-40960; int k=q>>6,n=q&63;
        float v=(k<64)?Wi[(64+n)*64+k]:Wh[(64+n)*64+k-64];
        int off=bidx(k,n,16);
        float h=tf32r(v); g_BzH[off]=h; g_BzL[off]=tf32r(v-h);
    }else if(i<53248){ int q=i-49152; int k=q>>6,n=q&63;
        float v=Wi[(128+n)*64+k];
        int off=bidx(k,n,8);
        float h=tf32r(v); g_BinH[off]=h; g_BinL[off]=tf32r(v-h);
    }else if(i<57344){ int q=i-53248; int k=q>>6,n=q&63;
        float v=Wh[(128+n)*64+k];
        int off=bidx(k,n,8);
        float h=tf32r(v); g_BhnH[off]=h; g_BhnL[off]=tf32r(v-h);
    }
}

__global__ void scan_kernel(){
    __shared__ int part[1024];
    int tid=threadIdx.x; const int CH=(NN+1023)/1024; int base=tid*CH; int s=0;
    for(int i=0;i<CH;++i){ int n=base+i; if(n<NN) s+=g_cnt4[n*4]+g_cnt4[n*4+1]+g_cnt4[n*4+2]+g_cnt4[n*4+3]; }
    part[tid]=s; __syncthreads();
    for(int off=1;off<1024;off<<=1){ int v=(tid>=off)?part[tid-off]:0; __syncthreads(); part[tid]+=v; __syncthreads(); }
    int run=(tid?part[tid-1]:0);
    for(int i=0;i<CH;++i){ int n=base+i; if(n<NN){ g_rowstart[n]=run; g_cursor[n]=run;
        run+=g_cnt4[n*4]+g_cnt4[n*4+1]+g_cnt4[n*4+2]+g_cnt4[n*4+3]; } }
    if(tid==1023) g_rowstart[NN]=part[1023];
}
__global__ void fill_kernel(const int* __restrict__ src,const int* __restrict__ dst,const int* __restrict__ ety){
    int e=blockIdx.x*blockDim.x+threadIdx.x;
    if(e<EE){ int pos=atomicAdd(&g_cursor[dst[e]],1); g_eidx[pos]=(src[e]<<2)|ety[e]; }
}

// ---------------- reduce: h0 = ann @ reduce_W + rb --------------------------------
__global__ __launch_bounds__(512,2) void reduce_mma(const float* __restrict__ ann,
        const float* __restrict__ rb){
    extern __shared__ float smf[];
    const int tid=threadIdx.x,w=tid>>5,lane=tid&31; const int n0=blockIdx.x*32;
    const int mtile=w>>3,nt=w&7;
    float C[4]={};
    for(int st=0;st<2;++st){
        for(int idx=tid;idx<1024;idx+=512){
            int row=idx>>5,k=(idx&31)<<2; int n=n0+row;
            float4 v=make_float4(0,0,0,0);
            if(n<NN) v=*(const float4*)&ann[(size_t)n*256+st*128+k];
            stA(smf,row,k,v.x); stA(smf,row,k+1,v.y); stA(smf,row,k+2,v.z); stA(smf,row,k+3,v.w);
        }
        fillB(smf,g_BredH+st*8192,g_BredL+st*8192,2048,tid);
        __syncthreads();
#pragma unroll
        for(int kc=0;kc<16;++kc) mmastep(C,smf,mtile*16+kc,nt*16+kc,nt,lane);
        __syncthreads();
    }
    const int g=lane>>2,tig=lane&3;
    int r0=n0+mtile*16+g, r1=r0+8, cb=nt*8+2*tig;
    float b0=rb[cb],b1=rb[cb+1];
    if(r0<NN){ float2 v={C[0]+b0,C[1]+b1};
        *(float2*)&g_h0[(size_t)r0*64+cb]=v; *(float2*)&g_h[(size_t)r0*64+cb]=v; }
    if(r1<NN){ float2 v={C[2]+b0,C[3]+b1};
        *(float2*)&g_h0[(size_t)r1*64+cb]=v; *(float2*)&g_h[(size_t)r1*64+cb]=v; }
}

// ---------------- agg: a = per-type CSR sums @ edge_W + cnt*edge_b ----------------
__global__ __launch_bounds__(512,2) void agg_mma(const float* __restrict__ eb){
    extern __shared__ float smf[];
    const int tid=threadIdx.x,w=tid>>5,lane=tid&31; const int n0=blockIdx.x*32;
    const int mtile=w>>3,nt=w&7;
    float2 st2[2],st3[2];
    for(int i=0;i<2;++i){
        int nloc=w*2+i, n=n0+nloc;
        float2 a0={0,0},a1={0,0},a2={0,0},a3={0,0};
        if(n<NN){
            int e=g_rowstart[n],re=g_rowstart[n+1];
            for(;e+4<=re;e+=4){
                int v0=g_eidx[e],v1=g_eidx[e+1],v2=g_eidx[e+2],v3=g_eidx[e+3];
                float2 x0=*(const float2*)&g_h[(size_t)(v0>>2)*64+(lane<<1)];
                float2 x1=*(const float2*)&g_h[(size_t)(v1>>2)*64+(lane<<1)];
                float2 x2=*(const float2*)&g_h[(size_t)(v2>>2)*64+(lane<<1)];
                float2 x3=*(const float2*)&g_h[(size_t)(v3>>2)*64+(lane<<1)];
                int t0=v0&3,t1=v1&3,t2=v2&3,t3=v3&3;
                if(t0==0){a0.x+=x0.x;a0.y+=x0.y;}else if(t0==1){a1.x+=x0.x;a1.y+=x0.y;}
                else if(t0==2){a2.x+=x0.x;a2.y+=x0.y;}else{a3.x+=x0.x;a3.y+=x0.y;}
                if(t1==0){a0.x+=x1.x;a0.y+=x1.y;}else if(t1==1){a1.x+=x1.x;a1.y+=x1.y;}
                else if(t1==2){a2.x+=x1.x;a2.y+=x1.y;}else{a3.x+=x1.x;a3.y+=x1.y;}
                if(t2==0){a0.x+=x2.x;a0.y+=x2.y;}else if(t2==1){a1.x+=x2.x;a1.y+=x2.y;}
                else if(t2==2){a2.x+=x2.x;a2.y+=x2.y;}else{a3.x+=x2.x;a3.y+=x2.y;}
                if(t3==0){a0.x+=x3.x;a0.y+=x3.y;}else if(t3==1){a1.x+=x3.x;a1.y+=x3.y;}
                else if(t3==2){a2.x+=x3.x;a2.y+=x3.y;}else{a3.x+=x3.x;a3.y+=x3.y;}
            }
            for(;e<re;++e){
                int v=g_eidx[e]; float2 x=*(const float2*)&g_h[(size_t)(v>>2)*64+(lane<<1)]; int t=v&3;
                if(t==0){a0.x+=x.x;a0.y+=x.y;}else if(t==1){a1.x+=x.x;a1.y+=x.y;}
                else if(t==2){a2.x+=x.x;a2.y+=x.y;}else{a3.x+=x.x;a3.y+=x.y;}
            }
        }
        int k=lane<<1;
        stA(smf,nloc,k,a0.x); stA(smf,nloc,k+1,a0.y);
        stA(smf,nloc,64+k,a1.x); stA(smf,nloc,64+k+1,a1.y);
        st2[i]=a2; st3[i]=a3;
    }
    float C[4]={};
    for(int st=0;st<2;++st){
        if(st==1){
            for(int i=0;i<2;++i){
                int nloc=w*2+i,k=lane<<1;
                stA(smf,nloc,k,st2[i].x); stA(smf,nloc,k+1,st2[i].y);
                stA(smf,nloc,64+k,st3[i].x); stA(smf,nloc,64+k+1,st3[i].y);
            }
        }
        fillB(smf,g_BedgeH+st*8192,g_BedgeL+st*8192,2048,tid);
        __syncthreads();
#pragma unroll
        for(int kc=0;kc<16;++kc) mmastep(C,smf,mtile*16+kc,nt*16+kc,nt,lane);
        __syncthreads();
    }
    const int g=lane>>2,tig=lane&3;
    int r0=n0+mtile*16+g, r1=r0+8, cb=nt*8+2*tig;
    float e00=eb[cb],e01=eb[cb+1],e10=eb[64+cb],e11=eb[64+cb+1];
    float e20=eb[128+cb],e21=eb[128+cb+1],e30=eb[192+cb],e31=eb[192+cb+1];
    if(r0<NN){ int4 c=*(const int4*)&g_cnt4[r0*4];
        float2 v={C[0]+c.x*e00+c.y*e10+c.z*e20+c.w*e30,
                  C[1]+c.x*e01+c.y*e11+c.z*e21+c.w*e31};
        *(float2*)&g_a[(size_t)r0*64+cb]=v; }
    if(r1<NN){ int4 c=*(const int4*)&g_cnt4[r1*4];
        float2 v={C[2]+c.x*e00+c.y*e10+c.z*e20+c.w*e30,
                  C[3]+c.x*e01+c.y*e11+c.z*e21+c.w*e31};
        *(float2*)&g_a[(size_t)r1*64+cb]=v; }
}

// ---------------- fused GRU -------------------------------------------------------
__global__ __launch_bounds__(512,2) void gru_mma(const float* __restrict__ bi,
        const float* __restrict__ bh_){
    extern __shared__ float smf[];
    const int tid=threadIdx.x,w=tid>>5,lane=tid&31; const int n0=blockIdx.x*32;
    const int mtile=w>>3,nt=w&7;
    for(int idx=tid;idx<1024;idx+=512){
        int row=idx>>5,k=(idx&31)<<2; int n=n0+row;
        float4 v=make_float4(0,0,0,0);
        if(n<NN) v=(k<64)?*(const float4*)&g_a[(size_t)n*64+k]:*(const float4*)&g_h[(size_t)n*64+k-64];
        stA(smf,row,k,v.x); stA(smf,row,k+1,v.y); stA(smf,row,k+2,v.z); stA(smf,row,k+3,v.w);
    }
    const int g=lane>>2,tig=lane&3;
    const int r0=n0+mtile*16+g, r1=r0+8, cb=nt*8+2*tig;
    float rv[4],tt[4],zv[4];

    // gate r (K=128)
    fillB(smf,g_BrH,g_BrL,2048,tid);
    __syncthreads();
    { float C[4]={};
#pragma unroll
      for(int kc=0;kc<16;++kc) mmastep(C,smf,mtile*16+kc,nt*16+kc,nt,lane);
#pragma unroll
      for(int i=0;i<4;++i){ int col=cb+(i&1);
          rv[i]=1.f/(1.f+expf(-(C[i]+bi[col]+bh_[col]))); } }
    __syncthreads();

    // gate hn (K=64, h half: A kc 8..15)
    fillB(smf,g_BhnH,g_BhnL,1024,tid);
    __syncthreads();
    { float C[4]={};
#pragma unroll
      for(int kc=0;kc<8;++kc) mmastep(C,smf,mtile*16+8+kc,nt*8+kc,nt,lane);
#pragma unroll
      for(int i=0;i<4;++i){ int col=cb+(i&1);
          tt[i]=rv[i]*(C[i]+bh_[128+col]); } }
    __syncthreads();

    // gate z (K=128)
    fillB(smf,g_BzH,g_BzL,2048,tid);
    __syncthreads();
    { float C[4]={};
#pragma unroll
      for(int kc=0;kc<16;++kc) mmastep(C,smf,mtile*16+kc,nt*16+kc,nt,lane);
#pragma unroll
      for(int i=0;i<4;++i){ int col=cb+(i&1);
          zv[i]=1.f/(1.f+expf(-(C[i]+bi[64+col]+bh_[64+col]))); } }
    __syncthreads();

    // gate in (K=64, a half: A kc 0..7) + epilogue
    fillB(smf,g_BinH,g_BinL,1024,tid);
    __syncthreads();
    { float C[4]={};
#pragma unroll
      for(int kc=0;kc<8;++kc) mmastep(C,smf,mtile*16+kc,nt*8+kc,nt,lane);
      if(r0<NN){
          float n0v=tanhf(C[0]+bi[128+cb]+tt[0]);
          float n1v=tanhf(C[1]+bi[128+cb+1]+tt[1]);
          float2 ho=*(const float2*)&g_h[(size_t)r0*64+cb];
          float2 hn={(1.f-zv[0])*n0v+zv[0]*ho.x,(1.f-zv[1])*n1v+zv[1]*ho.y};
          *(float2*)&g_h[(size_t)r0*64+cb]=hn;
      }
      if(r1<NN){
          float n0v=tanhf(C[2]+bi[128+cb]+tt[2]);
          float n1v=tanhf(C[3]+bi[128+cb+1]+tt[3]);
          float2 ho=*(const float2*)&g_h[(size_t)r1*64+cb];
          float2 hn={(1.f-zv[2])*n0v+zv[2]*ho.x,(1.f-zv[3])*n1v+zv[3]*ho.y};
          *(float2*)&g_h[(size_t)r1*64+cb]=hn;
      } }
}

// ---------------- attention pooling ------------------------------------------------
__device__ void atomicMaxFloat(float* addr,float v){
    int* ia=(int*)addr; int old=*ia;
    while(true){ float f=__int_as_float(old); if(f>=v) break;
        int as=old; old=atomicCAS(ia,as,__float_as_int(v)); if(old==as) break; }
}
__global__ __launch_bounds__(256) void gate_kernel(const int* __restrict__ gid,
        const float* __restrict__ gW,const float* __restrict__ gb){
    int gt=blockIdx.x*blockDim.x+threadIdx.x; int n=gt>>5; if(n>=NN) return;
    int lane=gt&31,j0=lane<<2;
    float4 fv=(j0<64)?*(const float4*)&g_h[(size_t)n*64+j0]:*(const float4*)&g_h0[(size_t)n*64+j0-64];
    float4 wv=*(const float4*)&gW[j0];
    float s=fv.x*wv.x+fv.y*wv.y+fv.z*wv.z+fv.w*wv.w;
#pragma unroll
    for(int o=16;o;o>>=1) s+=__shfl_xor_sync(0xffffffffu,s,o);
    if(lane==0){ float g=s+gb[0]; g_gate[n]=g; atomicMaxFloat(&g_gmax[gid[n]],g); }
}
__global__ __launch_bounds__(256) void pool_kernel(const int* __restrict__ gid){
    int gt=blockIdx.x*blockDim.x+threadIdx.x; int n=gt>>5; if(n>=NN) return;
    int lane=gt&31; int g=gid[n];
    float gm=g_gmax[g]; if(!isfinite(gm)) gm=0.f;
    float e=expf(g_gate[n]-gm);
    int j0=lane<<2;
    float4 fv=(j0<64)?*(const float4*)&g_h[(size_t)n*64+j0]:*(const float4*)&g_h0[(size_t)n*64+j0-64];
    float* rp=&g_rsum[g*128+j0];
    atomicAdd(rp,e*fv.x); atomicAdd(rp+1,e*fv.y); atomicAdd(rp+2,e*fv.z); atomicAdd(rp+3,e*fv.w);
    if(lane==0) atomicAdd(&g_den[g],e);
}
__global__ void out_kernel(const float* __restrict__ oW,const float* __restrict__ ob,float* __restrict__ out){
    int b=blockIdx.x,tid=threadIdx.x;
    float dn=g_den[b]; float inv=(dn>0.f)?(1.f/dn):0.f;
    float r=g_rsum[b*128+tid]*inv;
    float p0=r*oW[tid*2],p1=r*oW[tid*2+1];
#pragma unroll
    for(int o=16;o;o>>=1){ p0+=__shfl_xor_sync(0xffffffffu,p0,o); p1+=__shfl_xor_sync(0xffffffffu,p1,o); }
    __shared__ float s0[4],s1[4];
    if((tid&31)==0){ s0[tid>>5]=p0; s1[tid>>5]=p1; }
    __syncthreads();
    if(tid==0){ out[b*2]=s0[0]+s0[1]+s0[2]+s0[3]+ob[0]; out[b*2+1]=s1[0]+s1[1]+s1[2]+s1[3]+ob[1]; }
}
__global__ void tail_zero(){
    int i=blockIdx.x*blockDim.x+threadIdx.x;
    if(i<NN*4) g_cnt4[i]=0;
    if(i<BB*128) g_rsum[i]=0.f;
    if(i<BB){ g_den[i]=0.f; g_gmax[i]=__int_as_float(0xff800000); }
}

// ---------------- host orchestration -----------------------------------------------
extern "C" void kernel_launch(void* const* d_in,const int* in_sizes,int n_in,
                              void* d_out,int out_size){
    const float* ann=(const float*)d_in[0];
    const int* src=(const int*)d_in[1];
    const int* dst=(const int*)d_in[2];
    const int* ety=(const int*)d_in[3];
    const int* gid=(const int*)d_in[4];
    const float* reduce_W=(const float*)d_in[5];
    const float* reduce_b=(const float*)d_in[6];
    const float* edge_W=(const float*)d_in[7];
    const float* edge_b=(const float*)d_in[8];
    const float* gru_Wi=(const float*)d_in[9];
    const float* gru_bi=(const float*)d_in[10];
    const float* gru_Wh=(const float*)d_in[11];
    const float* gru_bh=(const float*)d_in[12];
    const float* gate_W=(const float*)d_in[13];
    const float* gate_b=(const float*)d_in[14];
    const float* out_W=(const float*)d_in[15];
    const float* out_b=(const float*)d_in[16];
    float* out=(float*)d_out;

    cudaFuncSetAttribute(reduce_mma,cudaFuncAttributeMaxDynamicSharedMemorySize,SMB);
    cudaFuncSetAttribute(agg_mma,cudaFuncAttributeMaxDynamicSharedMemorySize,SMB);
    cudaFuncSetAttribute(gru_mma,cudaFuncAttributeMaxDynamicSharedMemorySize,SMB);

    // harness adds 2 launches; ncu -s 5 -c 1 profiles OUR launch #4 = reduce_mma
    prep_kernel<<<(EE+255)/256,256>>>(dst,ety,reduce_W,edge_W,gru_Wi,gru_Wh);  // 1
    scan_kernel<<<1,1024>>>();                                                 // 2
    fill_kernel<<<(EE+255)/256,256>>>(src,dst,ety);                            // 3
    reduce_mma<<<GRID,512,SMB>>>(ann,reduce_b);                                // 4 <- profiled
    for(int s=0;s<NSTEPS;++s){
        agg_mma<<<GRID,512,SMB>>>(edge_b);
        gru_mma<<<GRID,512,SMB>>>(gru_bi,gru_bh);
    }
    gate_kernel<<<(NN*32+255)/256,256>>>(gid,gate_W,gate_b);
    pool_kernel<<<(NN*32+255)/256,256>>>(gid);
    out_kernel<<<BB,128>>>(out_W,out_b,out);
    tail_zero<<<(NN*4+255)/256,256>>>();
}

// round 10
// speedup vs baseline: 1.3777x; 1.2384x over previous
#include <cuda_runtime.h>
#include <math.h>
#include <stdint.h>

#define NN 100000
#define EE 1200000
#define BB 64
#define NSTEPS 6
#define GRID128 782    // ceil(NN/128)
#define GRID64  1563   // ceil(NN/64)

__device__ float g_h[NN * 64];
__device__ float g_h0[NN * 64];
__device__ float g_a[NN * 64];
__device__ int   g_rowstart[NN + 1];
__device__ int   g_cursor[NN];
__device__ int   g_eidx[EE];
__device__ int   g_cnt4[NN * 4];
__device__ float g_gate[NN];
__device__ float g_gmax[BB];
__device__ float g_den[BB];
__device__ float g_rsum[BB * 128];
// pre-split fragment-permuted B tiles, 4096 floats per 64-K stage
__device__ float g_BredH[16384],g_BredL[16384];   // 4 stages (K=256)
__device__ float g_BedgeH[16384],g_BedgeL[16384]; // 4 stages (types 0..3)
__device__ float g_BrH[8192],g_BrL[8192];         // 2 stages (K=128)
__device__ float g_BzH[8192],g_BzL[8192];         // 2 stages
__device__ float g_BinH[4096],g_BinL[4096];       // 1 stage (K=64, a-half)
__device__ float g_BhnH[4096],g_BhnL[4096];       // 1 stage (K=64, h-half)

__device__ __forceinline__ float tf32r(float x){ float y; asm("cvt.rna.tf32.f32 %0,%1;":"=f"(y):"f"(x)); return y; }

// fragment-permuted indices (m16n8k8 tf32), kcs = K/8 per region
__device__ __forceinline__ int aidx(int row,int k,int kcs){
    int mt=row>>4, r=row&15;
    return (((mt*kcs+(k>>3))<<5) + (((r&7)<<2)+(k&3)))*4 + ((r>>3)+(((k>>2)&1)<<1));
}
__device__ __forceinline__ int bidx(int k,int n,int kcs){
    return ((((n>>3)*kcs+(k>>3))<<5) + (((n&7)<<2)+(k&3)))*2 + ((k>>2)&1);
}
__device__ __forceinline__ void mma8(float* c,const uint32_t* a,const uint32_t* b){
    asm volatile("mma.sync.aligned.m16n8k8.row.col.f32.tf32.tf32.f32 "
        "{%0,%1,%2,%3},{%4,%5,%6,%7},{%8,%9},{%0,%1,%2,%3};"
        : "+f"(c[0]),"+f"(c[1]),"+f"(c[2]),"+f"(c[3])
        : "r"(a[0]),"r"(a[1]),"r"(a[2]),"r"(a[3]),"r"(b[0]),"r"(b[1]));
}
__device__ __forceinline__ void splitR(uint4 a,uint32_t* ah,uint32_t* al){
    const uint32_t* p=(const uint32_t*)&a;
#pragma unroll
    for(int i=0;i<4;++i){
        float v=__uint_as_float(p[i]); float h=tf32r(v);
        ah[i]=__float_as_uint(h); al[i]=__float_as_uint(tf32r(v-h));
    }
}
__device__ __forceinline__ void mma3r(float* c,const uint32_t* ah,const uint32_t* al,
                                      uint2 bh,uint2 bl){
    mma8(c,ah,(const uint32_t*)&bh);
    mma8(c,ah,(const uint32_t*)&bl);
    mma8(c,al,(const uint32_t*)&bh);
}
__device__ __forceinline__ uint4 ldA4(const float* smf,int frag,int lane){
    return *(const uint4*)&smf[(((frag<<5)+lane)<<2)];
}
__device__ __forceinline__ uint2 ldB2(const float* smf,int frag,int lane){
    return *(const uint2*)&smf[(((frag<<5)+lane)<<1)];
}
__device__ __forceinline__ void fillB8(float* smf,int obh,int obl,
        const float* BH,const float* BL,int tid){
    for(int i=tid;i<1024;i+=256){
        ((float4*)(smf+obh))[i]=((const float4*)BH)[i];
        ((float4*)(smf+obl))[i]=((const float4*)BL)[i];
    }
}

// ---------------- prep: histogram + weight pre-split/permute ---------------------
__global__ void prep_kernel(const int* __restrict__ dst,const int* __restrict__ ety,
        const float* __restrict__ rW,const float* __restrict__ eW,
        const float* __restrict__ Wi,const float* __restrict__ Wh){
    int i=blockIdx.x*blockDim.x+threadIdx.x;
    if(i<EE) atomicAdd(&g_cnt4[dst[i]*4+ety[i]],1);
    if(i<16384){ int k=i>>6,n=i&63; float v=rW[k*64+n];
        int off=(k>>6)*4096+bidx(k&63,n,8);
        float h=tf32r(v); g_BredH[off]=h; g_BredL[off]=tf32r(v-h);
    }else if(i<32768){ int q=i-16384; int k=q>>6,n=q&63;
        float v=eW[(k>>6)*4096+(k&63)*64+n];
        int off=(k>>6)*4096+bidx(k&63,n,8);
        float h=tf32r(v); g_BedgeH[off]=h; g_BedgeL[off]=tf32r(v-h);
    }else if(i<40960){ int q=i-32768; int k=q>>6,n=q&63;
        float v=(k<64)?Wi[n*64+k]:Wh[n*64+k-64];
        int off=(k>>6)*4096+bidx(k&63,n,8);
        float h=tf32r(v); g_BrH[off]=h; g_BrL[off]=tf32r(v-h);
    }else if(i<49152){ int q=i-40960; int k=q>>6,n=q&63;
        float v=(k<64)?Wi[(64+n)*64+k]:Wh[(64+n)*64+k-64];
        int off=(k>>6)*4096+bidx(k&63,n,8);
        float h=tf32r(v); g_BzH[off]=h; g_BzL[off]=tf32r(v-h);
    }else if(i<53248){ int q=i-49152; int k=q>>6,n=q&63;
        float v=Wi[(128+n)*64+k];
        int off=bidx(k,n,8);
        float h=tf32r(v); g_BinH[off]=h; g_BinL[off]=tf32r(v-h);
    }else if(i<57344){ int q=i-53248; int k=q>>6,n=q&63;
        float v=Wh[(128+n)*64+k];
        int off=bidx(k,n,8);
        float h=tf32r(v); g_BhnH[off]=h; g_BhnL[off]=tf32r(v-h);
    }
}
__global__ void scan_kernel(){
    __shared__ int part[1024];
    int tid=threadIdx.x; const int CH=(NN+1023)/1024; int base=tid*CH; int s=0;
    for(int i=0;i<CH;++i){ int n=base+i; if(n<NN) s+=g_cnt4[n*4]+g_cnt4[n*4+1]+g_cnt4[n*4+2]+g_cnt4[n*4+3]; }
    part[tid]=s; __syncthreads();
    for(int off=1;off<1024;off<<=1){ int v=(tid>=off)?part[tid-off]:0; __syncthreads(); part[tid]+=v; __syncthreads(); }
    int run=(tid?part[tid-1]:0);
    for(int i=0;i<CH;++i){ int n=base+i; if(n<NN){ g_rowstart[n]=run; g_cursor[n]=run;
        run+=g_cnt4[n*4]+g_cnt4[n*4+1]+g_cnt4[n*4+2]+g_cnt4[n*4+3]; } }
    if(tid==1023) g_rowstart[NN]=part[1023];
}
__global__ void fill_kernel(const int* __restrict__ src,const int* __restrict__ dst,const int* __restrict__ ety){
    int e=blockIdx.x*blockDim.x+threadIdx.x;
    if(e<EE){ int pos=atomicAdd(&g_cursor[dst[e]],1); g_eidx[pos]=(src[e]<<2)|ety[e]; }
}

// ---------------- reduce: h0 = ann @ reduce_W + rb -------------------------------
// M=128, warp tile m32n32; smem: A fp32 [0,8192) kcs=8 | Bh[8192,12288) | Bl[12288,16384)
#define R_OBH 8192
#define R_OBL 12288
#define SMB_R (16384*4)
__global__ __launch_bounds__(256,2) void reduce_mma(const float* __restrict__ ann,
        const float* __restrict__ rb){
    extern __shared__ float smf[];
    const int tid=threadIdx.x,w=tid>>5,lane=tid&31;
    const int wm=w>>1,wn=w&1,n0=blockIdx.x*128;
    float C[2][4][4]={};
    for(int st=0;st<4;++st){
        for(int idx=tid;idx<2048;idx+=256){
            int row=idx>>4,kq=(idx&15)<<2; int n=n0+row;
            float4 v=make_float4(0,0,0,0);
            if(n<NN) v=*(const float4*)&ann[(size_t)n*256+st*64+kq];
            smf[aidx(row,kq+0,8)]=v.x; smf[aidx(row,kq+1,8)]=v.y;
            smf[aidx(row,kq+2,8)]=v.z; smf[aidx(row,kq+3,8)]=v.w;
        }
        fillB8(smf,R_OBH,R_OBL,g_BredH+st*4096,g_BredL+st*4096,tid);
        __syncthreads();
#pragma unroll
        for(int kc=0;kc<8;++kc){
            uint4 af0=ldA4(smf,(wm*2+0)*8+kc,lane);
            uint4 af1=ldA4(smf,(wm*2+1)*8+kc,lane);
            uint32_t ah0[4],al0[4],ah1[4],al1[4];
            splitR(af0,ah0,al0); splitR(af1,ah1,al1);
#pragma unroll
            for(int j=0;j<4;++j){
                uint2 bh=ldB2(smf+R_OBH,(wn*4+j)*8+kc,lane);
                uint2 bl=ldB2(smf+R_OBL,(wn*4+j)*8+kc,lane);
                mma3r(C[0][j],ah0,al0,bh,bl);
                mma3r(C[1][j],ah1,al1,bh,bl);
            }
        }
        __syncthreads();
    }
    const int g=lane>>2,tig=lane&3;
#pragma unroll
    for(int i=0;i<2;++i){
        int base=n0+(wm*2+i)*16+g;
#pragma unroll
        for(int j=0;j<4;++j){
            int col=(wn*4+j)*8+tig*2;
            float b0=rb[col],b1=rb[col+1];
            if(base<NN){ float2 v={C[i][j][0]+b0,C[i][j][1]+b1};
                *(float2*)&g_h0[(size_t)base*64+col]=v; *(float2*)&g_h[(size_t)base*64+col]=v; }
            if(base+8<NN){ float2 v={C[i][j][2]+b0,C[i][j][3]+b1};
                *(float2*)&g_h0[(size_t)(base+8)*64+col]=v; *(float2*)&g_h[(size_t)(base+8)*64+col]=v; }
        }
    }
}

// ---------------- agg: a = per-type CSR sums @ edge_W + cnt*edge_b ---------------
// M=64, warp tile m16n32; smem: A fp32 [0,16384) kcs=32 | Bh[16384,20480) | Bl[20480,24576)
#define A_OBH 16384
#define A_OBL 20480
#define SMB_A (24576*4)
__global__ __launch_bounds__(256,2) void agg_mma(const float* __restrict__ eb){
    extern __shared__ float smf[];
    const int tid=threadIdx.x,w=tid>>5,lane=tid&31;
    const int wm=w>>1,wn=w&1,n0=blockIdx.x*64;
    // gather: 8 nodes per warp
    for(int i=0;i<8;++i){
        int nloc=w*8+i, n=n0+nloc;
        float2 a0={0,0},a1={0,0},a2={0,0},a3={0,0};
        if(n<NN){
            int e=g_rowstart[n],re=g_rowstart[n+1];
            for(;e+4<=re;e+=4){
                int v0=g_eidx[e],v1=g_eidx[e+1],v2=g_eidx[e+2],v3=g_eidx[e+3];
                float2 x0=*(const float2*)&g_h[(size_t)(v0>>2)*64+(lane<<1)];
                float2 x1=*(const float2*)&g_h[(size_t)(v1>>2)*64+(lane<<1)];
                float2 x2=*(const float2*)&g_h[(size_t)(v2>>2)*64+(lane<<1)];
                float2 x3=*(const float2*)&g_h[(size_t)(v3>>2)*64+(lane<<1)];
                int t0=v0&3,t1=v1&3,t2=v2&3,t3=v3&3;
                if(t0==0){a0.x+=x0.x;a0.y+=x0.y;}else if(t0==1){a1.x+=x0.x;a1.y+=x0.y;}
                else if(t0==2){a2.x+=x0.x;a2.y+=x0.y;}else{a3.x+=x0.x;a3.y+=x0.y;}
                if(t1==0){a0.x+=x1.x;a0.y+=x1.y;}else if(t1==1){a1.x+=x1.x;a1.y+=x1.y;}
                else if(t1==2){a2.x+=x1.x;a2.y+=x1.y;}else{a3.x+=x1.x;a3.y+=x1.y;}
                if(t2==0){a0.x+=x2.x;a0.y+=x2.y;}else if(t2==1){a1.x+=x2.x;a1.y+=x2.y;}
                else if(t2==2){a2.x+=x2.x;a2.y+=x2.y;}else{a3.x+=x2.x;a3.y+=x2.y;}
                if(t3==0){a0.x+=x3.x;a0.y+=x3.y;}else if(t3==1){a1.x+=x3.x;a1.y+=x3.y;}
                else if(t3==2){a2.x+=x3.x;a2.y+=x3.y;}else{a3.x+=x3.x;a3.y+=x3.y;}
            }
            for(;e<re;++e){
                int v=g_eidx[e]; float2 x=*(const float2*)&g_h[(size_t)(v>>2)*64+(lane<<1)]; int t=v&3;
                if(t==0){a0.x+=x.x;a0.y+=x.y;}else if(t==1){a1.x+=x.x;a1.y+=x.y;}
                else if(t==2){a2.x+=x.x;a2.y+=x.y;}else{a3.x+=x.x;a3.y+=x.y;}
            }
        }
        int k=lane<<1;
        smf[aidx(nloc,k,32)]=a0.x;       smf[aidx(nloc,k+1,32)]=a0.y;
        smf[aidx(nloc,64+k,32)]=a1.x;    smf[aidx(nloc,64+k+1,32)]=a1.y;
        smf[aidx(nloc,128+k,32)]=a2.x;   smf[aidx(nloc,128+k+1,32)]=a2.y;
        smf[aidx(nloc,192+k,32)]=a3.x;   smf[aidx(nloc,192+k+1,32)]=a3.y;
    }
    float C[4][4]={};
    for(int st=0;st<4;++st){
        if(st>0) __syncthreads();
        fillB8(smf,A_OBH,A_OBL,g_BedgeH+st*4096,g_BedgeL+st*4096,tid);
        __syncthreads();
#pragma unroll
        for(int kc=0;kc<8;++kc){
            uint4 af=ldA4(smf,wm*32+st*8+kc,lane);
            uint32_t ah[4],al[4]; splitR(af,ah,al);
#pragma unroll
            for(int j=0;j<4;++j){
                uint2 bh=ldB2(smf+A_OBH,(wn*4+j)*8+kc,lane);
                uint2 bl=ldB2(smf+A_OBL,(wn*4+j)*8+kc,lane);
                mma3r(C[j],ah,al,bh,bl);
            }
        }
    }
    const int g=lane>>2,tig=lane&3;
    int r0=n0+wm*16+g, r1=r0+8;
#pragma unroll
    for(int j=0;j<4;++j){
        int col=(wn*4+j)*8+tig*2;
        float e00=eb[col],e01=eb[col+1],e10=eb[64+col],e11=eb[64+col+1];
        float e20=eb[128+col],e21=eb[128+col+1],e30=eb[192+col],e31=eb[192+col+1];
        if(r0<NN){ int4 c=*(const int4*)&g_cnt4[r0*4];
            float2 v={C[j][0]+c.x*e00+c.y*e10+c.z*e20+c.w*e30,
                      C[j][1]+c.x*e01+c.y*e11+c.z*e21+c.w*e31};
            *(float2*)&g_a[(size_t)r0*64+col]=v; }
        if(r1<NN){ int4 c=*(const int4*)&g_cnt4[r1*4];
            float2 v={C[j][2]+c.x*e00+c.y*e10+c.z*e20+c.w*e30,
                      C[j][3]+c.x*e01+c.y*e11+c.z*e21+c.w*e31};
            *(float2*)&g_a[(size_t)r1*64+col]=v; }
    }
}

// ---------------- fused GRU -------------------------------------------------------
// M=64, warp tile m16n32; smem: A fp32 [0,8192) kcs=16 | Bh[8192,12288) | Bl[12288,16384)
#define G_OBH 8192
#define G_OBL 12288
#define SMB_G (16384*4)
__global__ __launch_bounds__(256,2) void gru_mma(const float* __restrict__ bi,
        const float* __restrict__ bh_){
    extern __shared__ float smf[];
    const int tid=threadIdx.x,w=tid>>5,lane=tid&31;
    const int wm=w>>1,wn=w&1,n0=blockIdx.x*64;
    for(int idx=tid;idx<1024;idx+=256){
        int row=idx>>4,kq=(idx&15)<<3; int n=n0+row;   // 8 floats per iter
        float4 v0=make_float4(0,0,0,0),v1=make_float4(0,0,0,0);
        if(n<NN){
            v0=(kq<64)?*(const float4*)&g_a[(size_t)n*64+kq]:*(const float4*)&g_h[(size_t)n*64+kq-64];
            int kq2=kq+4;
            v1=(kq2<64)?*(const float4*)&g_a[(size_t)n*64+kq2]:*(const float4*)&g_h[(size_t)n*64+kq2-64];
        }
        smf[aidx(row,kq+0,16)]=v0.x; smf[aidx(row,kq+1,16)]=v0.y;
        smf[aidx(row,kq+2,16)]=v0.z; smf[aidx(row,kq+3,16)]=v0.w;
        smf[aidx(row,kq+4,16)]=v1.x; smf[aidx(row,kq+5,16)]=v1.y;
        smf[aidx(row,kq+6,16)]=v1.z; smf[aidx(row,kq+7,16)]=v1.w;
    }
    const int g=lane>>2,tig=lane&3;
    const int r0=n0+wm*16+g, r1=r0+8;
    float rv[4][4],tt[4][4],zv[4][4];

#define GATE_MMA(C,BH,BL,NST,AOFF)                                        \
    for(int bst=0;bst<(NST);++bst){                                       \
        __syncthreads();                                                  \
        fillB8(smf,G_OBH,G_OBL,(BH)+bst*4096,(BL)+bst*4096,tid);          \
        __syncthreads();                                                  \
        _Pragma("unroll")                                                 \
        for(int kc=0;kc<8;++kc){                                          \
            uint4 af=ldA4(smf,wm*16+(AOFF)+bst*8+kc,lane);                \
            uint32_t ah[4],al[4]; splitR(af,ah,al);                       \
            _Pragma("unroll")                                             \
            for(int j=0;j<4;++j){                                         \
                uint2 bhv=ldB2(smf+G_OBH,(wn*4+j)*8+kc,lane);             \
                uint2 blv=ldB2(smf+G_OBL,(wn*4+j)*8+kc,lane);             \
                mma3r(C[j],ah,al,bhv,blv);                                \
            }                                                             \
        }                                                                 \
    }

    { float C[4][4]={}; GATE_MMA(C,g_BrH,g_BrL,2,0)
#pragma unroll
      for(int j=0;j<4;++j)
#pragma unroll
        for(int q=0;q<4;++q){ int col=(wn*4+j)*8+tig*2+(q&1);
            rv[j][q]=1.f/(1.f+expf(-(C[j][q]+bi[col]+bh_[col]))); } }
    { float C[4][4]={}; GATE_MMA(C,g_BhnH,g_BhnL,1,8)
#pragma unroll
      for(int j=0;j<4;++j)
#pragma unroll
        for(int q=0;q<4;++q){ int col=(wn*4+j)*8+tig*2+(q&1);
            tt[j][q]=rv[j][q]*(C[j][q]+bh_[128+col]); } }
    { float C[4][4]={}; GATE_MMA(C,g_BzH,g_BzL,2,0)
#pragma unroll
      for(int j=0;j<4;++j)
#pragma unroll
        for(int q=0;q<4;++q){ int col=(wn*4+j)*8+tig*2+(q&1);
            zv[j][q]=1.f/(1.f+expf(-(C[j][q]+bi[64+col]+bh_[64+col]))); } }
    { float C[4][4]={}; GATE_MMA(C,g_BinH,g_BinL,1,0)
#pragma unroll
      for(int j=0;j<4;++j){
          int col=(wn*4+j)*8+tig*2;
          if(r0<NN){
              float n0v=tanhf(C[j][0]+bi[128+col]+tt[j][0]);
              float n1v=tanhf(C[j][1]+bi[128+col+1]+tt[j][1]);
              float2 ho=*(const float2*)&g_h[(size_t)r0*64+col];
              float2 hn={(1.f-zv[j][0])*n0v+zv[j][0]*ho.x,(1.f-zv[j][1])*n1v+zv[j][1]*ho.y};
              *(float2*)&g_h[(size_t)r0*64+col]=hn;
          }
          if(r1<NN){
              float n0v=tanhf(C[j][2]+bi[128+col]+tt[j][2]);
              float n1v=tanhf(C[j][3]+bi[128+col+1]+tt[j][3]);
              float2 ho=*(const float2*)&g_h[(size_t)r1*64+col];
              float2 hn={(1.f-zv[j][2])*n0v+zv[j][2]*ho.x,(1.f-zv[j][3])*n1v+zv[j][3]*ho.y};
              *(float2*)&g_h[(size_t)r1*64+col]=hn;
          } } }
#undef GATE_MMA
}

// ---------------- attention pooling ------------------------------------------------
__device__ void atomicMaxFloat(float* addr,float v){
    int* ia=(int*)addr; int old=*ia;
    while(true){ float f=__int_as_float(old); if(f>=v) break;
        int as=old; old=atomicCAS(ia,as,__float_as_int(v)); if(old==as) break; }
}
__global__ __launch_bounds__(256) void gate_kernel(const int* __restrict__ gid,
        const float* __restrict__ gW,const float* __restrict__ gb){
    int gt=blockIdx.x*blockDim.x+threadIdx.x; int n=gt>>5; if(n>=NN) return;
    int lane=gt&31,j0=lane<<2;
    float4 fv=(j0<64)?*(const float4*)&g_h[(size_t)n*64+j0]:*(const float4*)&g_h0[(size_t)n*64+j0-64];
    float4 wv=*(const float4*)&gW[j0];
    float s=fv.x*wv.x+fv.y*wv.y+fv.z*wv.z+fv.w*wv.w;
#pragma unroll
    for(int o=16;o;o>>=1) s+=__shfl_xor_sync(0xffffffffu,s,o);
    if(lane==0){ float g=s+gb[0]; g_gate[n]=g; atomicMaxFloat(&g_gmax[gid[n]],g); }
}
__global__ __launch_bounds__(256) void pool_kernel(const int* __restrict__ gid){
    int gt=blockIdx.x*blockDim.x+threadIdx.x; int n=gt>>5; if(n>=NN) return;
    int lane=gt&31; int g=gid[n];
    float gm=g_gmax[g]; if(!isfinite(gm)) gm=0.f;
    float e=expf(g_gate[n]-gm);
    int j0=lane<<2;
    float4 fv=(j0<64)?*(const float4*)&g_h[(size_t)n*64+j0]:*(const float4*)&g_h0[(size_t)n*64+j0-64];
    float* rp=&g_rsum[g*128+j0];
    atomicAdd(rp,e*fv.x); atomicAdd(rp+1,e*fv.y); atomicAdd(rp+2,e*fv.z); atomicAdd(rp+3,e*fv.w);
    if(lane==0) atomicAdd(&g_den[g],e);
}
__global__ void out_kernel(const float* __restrict__ oW,const float* __restrict__ ob,float* __restrict__ out){
    int b=blockIdx.x,tid=threadIdx.x;
    float dn=g_den[b]; float inv=(dn>0.f)?(1.f/dn):0.f;
    float r=g_rsum[b*128+tid]*inv;
    float p0=r*oW[tid*2],p1=r*oW[tid*2+1];
#pragma unroll
    for(int o=16;o;o>>=1){ p0+=__shfl_xor_sync(0xffffffffu,p0,o); p1+=__shfl_xor_sync(0xffffffffu,p1,o); }
    __shared__ float s0[4],s1[4];
    if((tid&31)==0){ s0[tid>>5]=p0; s1[tid>>5]=p1; }
    __syncthreads();
    if(tid==0){ out[b*2]=s0[0]+s0[1]+s0[2]+s0[3]+ob[0]; out[b*2+1]=s1[0]+s1[1]+s1[2]+s1[3]+ob[1]; }
}
__global__ void tail_zero(){
    int i=blockIdx.x*blockDim.x+threadIdx.x;
    if(i<NN*4) g_cnt4[i]=0;
    if(i<BB*128) g_rsum[i]=0.f;
    if(i<BB){ g_den[i]=0.f; g_gmax[i]=__int_as_float(0xff800000); }
}

// ---------------- host orchestration -----------------------------------------------
extern "C" void kernel_launch(void* const* d_in,const int* in_sizes,int n_in,
                              void* d_out,int out_size){
    const float* ann=(const float*)d_in[0];
    const int* src=(const int*)d_in[1];
    const int* dst=(const int*)d_in[2];
    const int* ety=(const int*)d_in[3];
    const int* gid=(const int*)d_in[4];
    const float* reduce_W=(const float*)d_in[5];
    const float* reduce_b=(const float*)d_in[6];
    const float* edge_W=(const float*)d_in[7];
    const float* edge_b=(const float*)d_in[8];
    const float* gru_Wi=(const float*)d_in[9];
    const float* gru_bi=(const float*)d_in[10];
    const float* gru_Wh=(const float*)d_in[11];
    const float* gru_bh=(const float*)d_in[12];
    const float* gate_W=(const float*)d_in[13];
    const float* gate_b=(const float*)d_in[14];
    const float* out_W=(const float*)d_in[15];
    const float* out_b=(const float*)d_in[16];
    float* out=(float*)d_out;

    cudaFuncSetAttribute(reduce_mma,cudaFuncAttributeMaxDynamicSharedMemorySize,SMB_R);
    cudaFuncSetAttribute(agg_mma,cudaFuncAttributeMaxDynamicSharedMemorySize,SMB_A);
    cudaFuncSetAttribute(gru_mma,cudaFuncAttributeMaxDynamicSharedMemorySize,SMB_G);

    // harness adds 2 launches; ncu -s 5 -c 1 profiles OUR launch #4 = reduce_mma
    prep_kernel<<<(EE+255)/256,256>>>(dst,ety,reduce_W,edge_W,gru_Wi,gru_Wh);  // 1
    scan_kernel<<<1,1024>>>();                                                 // 2
    fill_kernel<<<(EE+255)/256,256>>>(src,dst,ety);                            // 3
    reduce_mma<<<GRID128,256,SMB_R>>>(ann,reduce_b);                           // 4 <- profiled
    for(int s=0;s<NSTEPS;++s){
        agg_mma<<<GRID64,256,SMB_A>>>(edge_b);
        gru_mma<<<GRID64,256,SMB_G>>>(gru_bi,gru_bh);
    }
    gate_kernel<<<(NN*32+255)/256,256>>>(gid,gate_W,gate_b);
    pool_kernel<<<(NN*32+255)/256,256>>>(gid);
    out_kernel<<<BB,128>>>(out_W,out_b,out);
    tail_zero<<<(NN*4+255)/256,256>>>();
}

// round 11
// speedup vs baseline: 1.4322x; 1.0396x over previous
#include <cuda_runtime.h>
#include <math.h>
#include <stdint.h>

#define NN 100000
#define EE 1200000
#define BB 64
#define NSTEPS 6
#define GRID128 782
#define GRID64  1563

__device__ float g_hA[NN * 64];
__device__ float g_hB[NN * 64];
__device__ float g_h0[NN * 64];
__device__ int   g_rowstart[NN + 1];
__device__ int   g_cursor[NN];
__device__ int   g_eidx[EE];
__device__ int   g_cnt4[NN * 4];
__device__ float g_gate[NN];
__device__ float g_gmax[BB];
__device__ float g_den[BB];
__device__ float g_rsum[BB * 128];
// pre-split fragment-permuted B tiles, 4096 floats per 64-K stage
__device__ float g_BredH[16384],g_BredL[16384];
__device__ float g_BedgeH[16384],g_BedgeL[16384];
__device__ float g_BrH[8192],g_BrL[8192];
__device__ float g_BzH[8192],g_BzL[8192];
__device__ float g_BinH[4096],g_BinL[4096];
__device__ float g_BhnH[4096],g_BhnL[4096];

__device__ __forceinline__ float tf32r(float x){ float y; asm("cvt.rna.tf32.f32 %0,%1;":"=f"(y):"f"(x)); return y; }

__device__ __forceinline__ int aidx(int row,int k,int kcs){
    int mt=row>>4, r=row&15;
    return (((mt*kcs+(k>>3))<<5) + (((r&7)<<2)+(k&3)))*4 + ((r>>3)+(((k>>2)&1)<<1));
}
__device__ __forceinline__ int bidx(int k,int n,int kcs){
    return ((((n>>3)*kcs+(k>>3))<<5) + (((n&7)<<2)+(k&3)))*2 + ((k>>2)&1);
}
__device__ __forceinline__ void mma8(float* c,const uint32_t* a,const uint32_t* b){
    asm volatile("mma.sync.aligned.m16n8k8.row.col.f32.tf32.tf32.f32 "
        "{%0,%1,%2,%3},{%4,%5,%6,%7},{%8,%9},{%0,%1,%2,%3};"
        : "+f"(c[0]),"+f"(c[1]),"+f"(c[2]),"+f"(c[3])
        : "r"(a[0]),"r"(a[1]),"r"(a[2]),"r"(a[3]),"r"(b[0]),"r"(b[1]));
}
__device__ __forceinline__ void splitR(uint4 a,uint32_t* ah,uint32_t* al){
    const uint32_t* p=(const uint32_t*)&a;
#pragma unroll
    for(int i=0;i<4;++i){
        float v=__uint_as_float(p[i]); float h=tf32r(v);
        ah[i]=__float_as_uint(h); al[i]=__float_as_uint(tf32r(v-h));
    }
}
__device__ __forceinline__ void mma3r(float* c,const uint32_t* ah,const uint32_t* al,
                                      uint2 bh,uint2 bl){
    mma8(c,ah,(const uint32_t*)&bh);
    mma8(c,ah,(const uint32_t*)&bl);
    mma8(c,al,(const uint32_t*)&bh);
}
__device__ __forceinline__ uint4 ldA4(const float* smf,int frag,int lane){
    return *(const uint4*)&smf[(((frag<<5)+lane)<<2)];
}
__device__ __forceinline__ uint2 ldB2(const float* smf,int frag,int lane){
    return *(const uint2*)&smf[(((frag<<5)+lane)<<1)];
}
__device__ __forceinline__ void fillB8(float* smf,int obh,int obl,
        const float* BH,const float* BL,int tid){
    for(int i=tid;i<1024;i+=256){
        ((float4*)(smf+obh))[i]=((const float4*)BH)[i];
        ((float4*)(smf+obl))[i]=((const float4*)BL)[i];
    }
}

// ---------------- prep: histogram + weight pre-split/permute ---------------------
__global__ void prep_kernel(const int* __restrict__ dst,const int* __restrict__ ety,
        const float* __restrict__ rW,const float* __restrict__ eW,
        const float* __restrict__ Wi,const float* __restrict__ Wh){
    int i=blockIdx.x*blockDim.x+threadIdx.x;
    if(i<EE) atomicAdd(&g_cnt4[dst[i]*4+ety[i]],1);
    if(i<16384){ int k=i>>6,n=i&63; float v=rW[k*64+n];
        int off=(k>>6)*4096+bidx(k&63,n,8);
        float h=tf32r(v); g_BredH[off]=h; g_BredL[off]=tf32r(v-h);
    }else if(i<32768){ int q=i-16384; int k=q>>6,n=q&63;
        float v=eW[(k>>6)*4096+(k&63)*64+n];
        int off=(k>>6)*4096+bidx(k&63,n,8);
        float h=tf32r(v); g_BedgeH[off]=h; g_BedgeL[off]=tf32r(v-h);
    }else if(i<40960){ int q=i-32768; int k=q>>6,n=q&63;
        float v=(k<64)?Wi[n*64+k]:Wh[n*64+k-64];
        int off=(k>>6)*4096+bidx(k&63,n,8);
        float h=tf32r(v); g_BrH[off]=h; g_BrL[off]=tf32r(v-h);
    }else if(i<49152){ int q=i-40960; int k=q>>6,n=q&63;
        float v=(k<64)?Wi[(64+n)*64+k]:Wh[(64+n)*64+k-64];
        int off=(k>>6)*4096+bidx(k&63,n,8);
        float h=tf32r(v); g_BzH[off]=h; g_BzL[off]=tf32r(v-h);
    }else if(i<53248){ int q=i-49152; int k=q>>6,n=q&63;
        float v=Wi[(128+n)*64+k];
        int off=bidx(k,n,8);
        float h=tf32r(v); g_BinH[off]=h; g_BinL[off]=tf32r(v-h);
    }else if(i<57344){ int q=i-53248; int k=q>>6,n=q&63;
        float v=Wh[(128+n)*64+k];
        int off=bidx(k,n,8);
        float h=tf32r(v); g_BhnH[off]=h; g_BhnL[off]=tf32r(v-h);
    }
}
__global__ void scan_kernel(){
    __shared__ int part[1024];
    int tid=threadIdx.x; const int CH=(NN+1023)/1024; int base=tid*CH; int s=0;
    for(int i=0;i<CH;++i){ int n=base+i; if(n<NN) s+=g_cnt4[n*4]+g_cnt4[n*4+1]+g_cnt4[n*4+2]+g_cnt4[n*4+3]; }
    part[tid]=s; __syncthreads();
    for(int off=1;off<1024;off<<=1){ int v=(tid>=off)?part[tid-off]:0; __syncthreads(); part[tid]+=v; __syncthreads(); }
    int run=(tid?part[tid-1]:0);
    for(int i=0;i<CH;++i){ int n=base+i; if(n<NN){ g_rowstart[n]=run; g_cursor[n]=run;
        run+=g_cnt4[n*4]+g_cnt4[n*4+1]+g_cnt4[n*4+2]+g_cnt4[n*4+3]; } }
    if(tid==1023) g_rowstart[NN]=part[1023];
}
__global__ void fill_kernel(const int* __restrict__ src,const int* __restrict__ dst,const int* __restrict__ ety){
    int e=blockIdx.x*blockDim.x+threadIdx.x;
    if(e<EE){ int pos=atomicAdd(&g_cursor[dst[e]],1); g_eidx[pos]=(src[e]<<2)|ety[e]; }
}

// ---------------- reduce: h0 = ann @ reduce_W + rb -------------------------------
#define R_OBH 8192
#define R_OBL 12288
#define SMB_R (16384*4)
__global__ __launch_bounds__(256,2) void reduce_mma(const float* __restrict__ ann,
        const float* __restrict__ rb){
    extern __shared__ float smf[];
    const int tid=threadIdx.x,w=tid>>5,lane=tid&31;
    const int wm=w>>1,wn=w&1,n0=blockIdx.x*128;
    float C[2][4][4]={};
    for(int st=0;st<4;++st){
        for(int idx=tid;idx<2048;idx+=256){
            int row=idx>>4,kq=(idx&15)<<2; int n=n0+row;
            float4 v=make_float4(0,0,0,0);
            if(n<NN) v=*(const float4*)&ann[(size_t)n*256+st*64+kq];
            smf[aidx(row,kq+0,8)]=v.x; smf[aidx(row,kq+1,8)]=v.y;
            smf[aidx(row,kq+2,8)]=v.z; smf[aidx(row,kq+3,8)]=v.w;
        }
        fillB8(smf,R_OBH,R_OBL,g_BredH+st*4096,g_BredL+st*4096,tid);
        __syncthreads();
#pragma unroll
        for(int kc=0;kc<8;++kc){
            uint4 af0=ldA4(smf,(wm*2+0)*8+kc,lane);
            uint4 af1=ldA4(smf,(wm*2+1)*8+kc,lane);
            uint32_t ah0[4],al0[4],ah1[4],al1[4];
            splitR(af0,ah0,al0); splitR(af1,ah1,al1);
#pragma unroll
            for(int j=0;j<4;++j){
                uint2 bh=ldB2(smf+R_OBH,(wn*4+j)*8+kc,lane);
                uint2 bl=ldB2(smf+R_OBL,(wn*4+j)*8+kc,lane);
                mma3r(C[0][j],ah0,al0,bh,bl);
                mma3r(C[1][j],ah1,al1,bh,bl);
            }
        }
        __syncthreads();
    }
    const int g=lane>>2,tig=lane&3;
#pragma unroll
    for(int i=0;i<2;++i){
        int base=n0+(wm*2+i)*16+g;
#pragma unroll
        for(int j=0;j<4;++j){
            int col=(wn*4+j)*8+tig*2;
            float b0=rb[col],b1=rb[col+1];
            if(base<NN){ float2 v={C[i][j][0]+b0,C[i][j][1]+b1};
                *(float2*)&g_h0[(size_t)base*64+col]=v; *(float2*)&g_hA[(size_t)base*64+col]=v; }
            if(base+8<NN){ float2 v={C[i][j][2]+b0,C[i][j][3]+b1};
                *(float2*)&g_h0[(size_t)(base+8)*64+col]=v; *(float2*)&g_hA[(size_t)(base+8)*64+col]=v; }
        }
    }
}

// ---------------- fused step: gather + edge mma + GRU ----------------------------
// M=64; smem: aggA fp32 [0,16384) kcs=32  /  gruA reuses [0,8192) kcs=16
//        Bh[16384,20480) Bl[20480,24576)
#define S_OBH 16384
#define S_OBL 20480
#define SMB_S (24576*4)
__global__ __launch_bounds__(256,2) void step_mma(
        const float* __restrict__ hin, float* __restrict__ hout,
        const float* __restrict__ eb, const float* __restrict__ bi,
        const float* __restrict__ bh_){
    extern __shared__ float smf[];
    const int tid=threadIdx.x,w=tid>>5,lane=tid&31;
    const int wm=w>>1,wn=w&1,n0=blockIdx.x*64;

    // ---- gather (MLP 8) into aggA ----
    for(int i=0;i<8;++i){
        int nloc=w*8+i, n=n0+nloc;
        float2 a0={0,0},a1={0,0},a2={0,0},a3={0,0};
        if(n<NN){
            int e=g_rowstart[n],re=g_rowstart[n+1];
            for(;e+8<=re;e+=8){
                int vv[8];
#pragma unroll
                for(int u=0;u<8;++u) vv[u]=g_eidx[e+u];
                float2 xx[8];
#pragma unroll
                for(int u=0;u<8;++u) xx[u]=*(const float2*)&hin[(size_t)(vv[u]>>2)*64+(lane<<1)];
#pragma unroll
                for(int u=0;u<8;++u){
                    int t=vv[u]&3;
                    if(t==0){a0.x+=xx[u].x;a0.y+=xx[u].y;}
                    else if(t==1){a1.x+=xx[u].x;a1.y+=xx[u].y;}
                    else if(t==2){a2.x+=xx[u].x;a2.y+=xx[u].y;}
                    else{a3.x+=xx[u].x;a3.y+=xx[u].y;}
                }
            }
            for(;e<re;++e){
                int v=g_eidx[e]; float2 x=*(const float2*)&hin[(size_t)(v>>2)*64+(lane<<1)]; int t=v&3;
                if(t==0){a0.x+=x.x;a0.y+=x.y;}else if(t==1){a1.x+=x.x;a1.y+=x.y;}
                else if(t==2){a2.x+=x.x;a2.y+=x.y;}else{a3.x+=x.x;a3.y+=x.y;}
            }
        }
        int k=lane<<1;
        smf[aidx(nloc,k,32)]=a0.x;       smf[aidx(nloc,k+1,32)]=a0.y;
        smf[aidx(nloc,64+k,32)]=a1.x;    smf[aidx(nloc,64+k+1,32)]=a1.y;
        smf[aidx(nloc,128+k,32)]=a2.x;   smf[aidx(nloc,128+k+1,32)]=a2.y;
        smf[aidx(nloc,192+k,32)]=a3.x;   smf[aidx(nloc,192+k+1,32)]=a3.y;
    }

    // ---- edge-type mma: a = sums @ edge_W ----
    float C[4][4]={};
    for(int st=0;st<4;++st){
        if(st>0) __syncthreads();
        fillB8(smf,S_OBH,S_OBL,g_BedgeH+st*4096,g_BedgeL+st*4096,tid);
        __syncthreads();
#pragma unroll
        for(int kc=0;kc<8;++kc){
            uint4 af=ldA4(smf,wm*32+st*8+kc,lane);
            uint32_t ah[4],al[4]; splitR(af,ah,al);
#pragma unroll
            for(int j=0;j<4;++j){
                uint2 bh=ldB2(smf+S_OBH,(wn*4+j)*8+kc,lane);
                uint2 bl=ldB2(smf+S_OBL,(wn*4+j)*8+kc,lane);
                mma3r(C[j],ah,al,bh,bl);
            }
        }
    }
    __syncthreads();   // protect gruA overwrite vs other warps' st=3 reads

    // ---- build gruA = [a | h] (K=128, kcs=16) ----
    const int g=lane>>2,tig=lane&3;
    const int r0loc=wm*16+g, r1loc=r0loc+8;
    const int gr0=n0+r0loc, gr1=n0+r1loc;
    {
        int4 c0=make_int4(0,0,0,0),c1=make_int4(0,0,0,0);
        if(gr0<NN) c0=*(const int4*)&g_cnt4[gr0*4];
        if(gr1<NN) c1=*(const int4*)&g_cnt4[gr1*4];
#pragma unroll
        for(int j=0;j<4;++j){
            int col=(wn*4+j)*8+tig*2;
            float e00=eb[col],e01=eb[col+1],e10=eb[64+col],e11=eb[64+col+1];
            float e20=eb[128+col],e21=eb[128+col+1],e30=eb[192+col],e31=eb[192+col+1];
            smf[aidx(r0loc,col,16)]  =C[j][0]+c0.x*e00+c0.y*e10+c0.z*e20+c0.w*e30;
            smf[aidx(r0loc,col+1,16)]=C[j][1]+c0.x*e01+c0.y*e11+c0.z*e21+c0.w*e31;
            smf[aidx(r1loc,col,16)]  =C[j][2]+c1.x*e00+c1.y*e10+c1.z*e20+c1.w*e30;
            smf[aidx(r1loc,col+1,16)]=C[j][3]+c1.x*e01+c1.y*e11+c1.z*e21+c1.w*e31;
        }
    }
    for(int idx=tid;idx<1024;idx+=256){
        int row=idx>>4,kq=(idx&15)<<2; int n=n0+row;
        float4 v=make_float4(0,0,0,0);
        if(n<NN) v=*(const float4*)&hin[(size_t)n*64+kq];
        smf[aidx(row,64+kq+0,16)]=v.x; smf[aidx(row,64+kq+1,16)]=v.y;
        smf[aidx(row,64+kq+2,16)]=v.z; smf[aidx(row,64+kq+3,16)]=v.w;
    }

    float rv[4][4],tt[4][4],zv[4][4];
#define GATE_MMA(C,BH,BL,NST,AOFF)                                        \
    for(int bst=0;bst<(NST);++bst){                                       \
        __syncthreads();                                                  \
        fillB8(smf,S_OBH,S_OBL,(BH)+bst*4096,(BL)+bst*4096,tid);          \
        __syncthreads();                                                  \
        _Pragma("unroll")                                                 \
        for(int kc=0;kc<8;++kc){                                          \
            uint4 af=ldA4(smf,wm*16+(AOFF)+bst*8+kc,lane);                \
            uint32_t ah[4],al[4]; splitR(af,ah,al);                       \
            _Pragma("unroll")                                             \
            for(int j=0;j<4;++j){                                         \
                uint2 bhv=ldB2(smf+S_OBH,(wn*4+j)*8+kc,lane);             \
                uint2 blv=ldB2(smf+S_OBL,(wn*4+j)*8+kc,lane);             \
                mma3r(C[j],ah,al,bhv,blv);                                \
            }                                                             \
        }                                                                 \
    }

    { float Cg[4][4]={}; GATE_MMA(Cg,g_BrH,g_BrL,2,0)
#pragma unroll
      for(int j=0;j<4;++j)
#pragma unroll
        for(int q=0;q<4;++q){ int col=(wn*4+j)*8+tig*2+(q&1);
            rv[j][q]=1.f/(1.f+expf(-(Cg[j][q]+bi[col]+bh_[col]))); } }
    { float Cg[4][4]={}; GATE_MMA(Cg,g_BhnH,g_BhnL,1,8)
#pragma unroll
      for(int j=0;j<4;++j)
#pragma unroll
        for(int q=0;q<4;++q){ int col=(wn*4+j)*8+tig*2+(q&1);
            tt[j][q]=rv[j][q]*(Cg[j][q]+bh_[128+col]); } }
    { float Cg[4][4]={}; GATE_MMA(Cg,g_BzH,g_BzL,2,0)
#pragma unroll
      for(int j=0;j<4;++j)
#pragma unroll
        for(int q=0;q<4;++q){ int col=(wn*4+j)*8+tig*2+(q&1);
            zv[j][q]=1.f/(1.f+expf(-(Cg[j][q]+bi[64+col]+bh_[64+col]))); } }
    { float Cg[4][4]={}; GATE_MMA(Cg,g_BinH,g_BinL,1,0)
#pragma unroll
      for(int j=0;j<4;++j){
          int col=(wn*4+j)*8+tig*2;
          if(gr0<NN){
              float h0v=smf[aidx(r0loc,64+col,16)];
              float h1v=smf[aidx(r0loc,64+col+1,16)];
              float n0v=tanhf(Cg[j][0]+bi[128+col]+tt[j][0]);
              float n1v=tanhf(Cg[j][1]+bi[128+col+1]+tt[j][1]);
              float2 hn={(1.f-zv[j][0])*n0v+zv[j][0]*h0v,(1.f-zv[j][1])*n1v+zv[j][1]*h1v};
              *(float2*)&hout[(size_t)gr0*64+col]=hn;
          }
          if(gr1<NN){
              float h0v=smf[aidx(r1loc,64+col,16)];
              float h1v=smf[aidx(r1loc,64+col+1,16)];
              float n0v=tanhf(Cg[j][2]+bi[128+col]+tt[j][2]);
              float n1v=tanhf(Cg[j][3]+bi[128+col+1]+tt[j][3]);
              float2 hn={(1.f-zv[j][2])*n0v+zv[j][2]*h0v,(1.f-zv[j][3])*n1v+zv[j][3]*h1v};
              *(float2*)&hout[(size_t)gr1*64+col]=hn;
          } } }
#undef GATE_MMA
}

// ---------------- attention pooling ------------------------------------------------
__device__ void atomicMaxFloat(float* addr,float v){
    int* ia=(int*)addr; int old=*ia;
    while(true){ float f=__int_as_float(old); if(f>=v) break;
        int as=old; old=atomicCAS(ia,as,__float_as_int(v)); if(old==as) break; }
}
__global__ __launch_bounds__(256) void gate_kernel(const int* __restrict__ gid,
        const float* __restrict__ gW,const float* __restrict__ gb){
    int gt=blockIdx.x*blockDim.x+threadIdx.x; int n=gt>>5; if(n>=NN) return;
    int lane=gt&31,j0=lane<<2;
    float4 fv=(j0<64)?*(const float4*)&g_hA[(size_t)n*64+j0]:*(const float4*)&g_h0[(size_t)n*64+j0-64];
    float4 wv=*(const float4*)&gW[j0];
    float s=fv.x*wv.x+fv.y*wv.y+fv.z*wv.z+fv.w*wv.w;
#pragma unroll
    for(int o=16;o;o>>=1) s+=__shfl_xor_sync(0xffffffffu,s,o);
    if(lane==0){ float g=s+gb[0]; g_gate[n]=g; atomicMaxFloat(&g_gmax[gid[n]],g); }
}
__global__ __launch_bounds__(256) void pool_kernel(const int* __restrict__ gid){
    int gt=blockIdx.x*blockDim.x+threadIdx.x; int n=gt>>5; if(n>=NN) return;
    int lane=gt&31; int g=gid[n];
    float gm=g_gmax[g]; if(!isfinite(gm)) gm=0.f;
    float e=expf(g_gate[n]-gm);
    int j0=lane<<2;
    float4 fv=(j0<64)?*(const float4*)&g_hA[(size_t)n*64+j0]:*(const float4*)&g_h0[(size_t)n*64+j0-64];
    float* rp=&g_rsum[g*128+j0];
    atomicAdd(rp,e*fv.x); atomicAdd(rp+1,e*fv.y); atomicAdd(rp+2,e*fv.z); atomicAdd(rp+3,e*fv.w);
    if(lane==0) atomicAdd(&g_den[g],e);
}
__global__ void out_kernel(const float* __restrict__ oW,const float* __restrict__ ob,float* __restrict__ out){
    int b=blockIdx.x,tid=threadIdx.x;
    float dn=g_den[b]; float inv=(dn>0.f)?(1.f/dn):0.f;
    float r=g_rsum[b*128+tid]*inv;
    float p0=r*oW[tid*2],p1=r*oW[tid*2+1];
#pragma unroll
    for(int o=16;o;o>>=1){ p0+=__shfl_xor_sync(0xffffffffu,p0,o); p1+=__shfl_xor_sync(0xffffffffu,p1,o); }
    __shared__ float s0[4],s1[4];
    if((tid&31)==0){ s0[tid>>5]=p0; s1[tid>>5]=p1; }
    __syncthreads();
    if(tid==0){ out[b*2]=s0[0]+s0[1]+s0[2]+s0[3]+ob[0]; out[b*2+1]=s1[0]+s1[1]+s1[2]+s1[3]+ob[1]; }
}
__global__ void tail_zero(){
    int i=blockIdx.x*blockDim.x+threadIdx.x;
    if(i<NN*4) g_cnt4[i]=0;
    if(i<BB*128) g_rsum[i]=0.f;
    if(i<BB){ g_den[i]=0.f; g_gmax[i]=__int_as_float(0xff800000); }
}

// ---------------- host orchestration -----------------------------------------------
extern "C" void kernel_launch(void* const* d_in,const int* in_sizes,int n_in,
                              void* d_out,int out_size){
    const float* ann=(const float*)d_in[0];
    const int* src=(const int*)d_in[1];
    const int* dst=(const int*)d_in[2];
    const int* ety=(const int*)d_in[3];
    const int* gid=(const int*)d_in[4];
    const float* reduce_W=(const float*)d_in[5];
    const float* reduce_b=(const float*)d_in[6];
    const float* edge_W=(const float*)d_in[7];
    const float* edge_b=(const float*)d_in[8];
    const float* gru_Wi=(const float*)d_in[9];
    const float* gru_bi=(const float*)d_in[10];
    const float* gru_Wh=(const float*)d_in[11];
    const float* gru_bh=(const float*)d_in[12];
    const float* gate_W=(const float*)d_in[13];
    const float* gate_b=(const float*)d_in[14];
    const float* out_W=(const float*)d_in[15];
    const float* out_b=(const float*)d_in[16];
    float* out=(float*)d_out;

    float *hA,*hB;
    cudaGetSymbolAddress((void**)&hA,g_hA);
    cudaGetSymbolAddress((void**)&hB,g_hB);

    cudaFuncSetAttribute(reduce_mma,cudaFuncAttributeMaxDynamicSharedMemorySize,SMB_R);
    cudaFuncSetAttribute(step_mma,cudaFuncAttributeMaxDynamicSharedMemorySize,SMB_S);

    prep_kernel<<<(EE+255)/256,256>>>(dst,ety,reduce_W,edge_W,gru_Wi,gru_Wh);
    scan_kernel<<<1,1024>>>();
    fill_kernel<<<(EE+255)/256,256>>>(src,dst,ety);
    reduce_mma<<<GRID128,256,SMB_R>>>(ann,reduce_b);
    for(int s=0;s<NSTEPS;++s){
        const float* hin=(s&1)?hB:hA;
        float* hout=(s&1)?hA:hB;
        step_mma<<<GRID64,256,SMB_S>>>(hin,hout,edge_b,gru_bi,gru_bh);
    }
    // NSTEPS=6 even: final h lands in g_hA after step 5 (B->A)
    gate_kernel<<<(NN*32+255)/256,256>>>(gid,gate_W,gate_b);
    pool_kernel<<<(NN*32+255)/256,256>>>(gid);
    out_kernel<<<BB,128>>>(out_W,out_b,out);
    tail_zero<<<(NN*4+255)/256,256>>>();
}

// round 12
// speedup vs baseline: 1.4819x; 1.0347x over previous
#include <cuda_runtime.h>
#include <math.h>
#include <stdint.h>

#define NN 100000
#define EE 1200000
#define BB 64
#define NSTEPS 6
#define GRID128 782
#define GRID64  1563

__device__ float g_hA[NN * 64];
__device__ float g_hB[NN * 64];
__device__ float g_h0[NN * 64];
__device__ int   g_rowstart[NN + 1];
__device__ int   g_cursor[NN];
__device__ int   g_eidx[EE];
__device__ int   g_cnt4[NN * 4];
__device__ float g_gate[NN];
__device__ float g_gmax[BB];
__device__ float g_den[BB];
__device__ float g_rsum[BB * 128];
__device__ float g_BredH[16384],g_BredL[16384];
__device__ float g_BedgeH[16384],g_BedgeL[16384];
__device__ float g_BrH[8192],g_BrL[8192];
__device__ float g_BzH[8192],g_BzL[8192];
__device__ float g_BinH[4096],g_BinL[4096];
__device__ float g_BhnH[4096],g_BhnL[4096];

__device__ __forceinline__ float tf32r(float x){ float y; asm("cvt.rna.tf32.f32 %0,%1;":"=f"(y):"f"(x)); return y; }

__device__ __forceinline__ int aidx(int row,int k,int kcs){
    int mt=row>>4, r=row&15;
    return (((mt*kcs+(k>>3))<<5) + (((r&7)<<2)+(k&3)))*4 + ((r>>3)+(((k>>2)&1)<<1));
}
__device__ __forceinline__ int bidx(int k,int n,int kcs){
    return ((((n>>3)*kcs+(k>>3))<<5) + (((n&7)<<2)+(k&3)))*2 + ((k>>2)&1);
}
__device__ __forceinline__ void mma8(float* c,const uint32_t* a,const uint32_t* b){
    asm volatile("mma.sync.aligned.m16n8k8.row.col.f32.tf32.tf32.f32 "
        "{%0,%1,%2,%3},{%4,%5,%6,%7},{%8,%9},{%0,%1,%2,%3};"
        : "+f"(c[0]),"+f"(c[1]),"+f"(c[2]),"+f"(c[3])
        : "r"(a[0]),"r"(a[1]),"r"(a[2]),"r"(a[3]),"r"(b[0]),"r"(b[1]));
}
__device__ __forceinline__ void splitR(uint4 a,uint32_t* ah,uint32_t* al){
    const uint32_t* p=(const uint32_t*)&a;
#pragma unroll
    for(int i=0;i<4;++i){
        float v=__uint_as_float(p[i]); float h=tf32r(v);
        ah[i]=__float_as_uint(h); al[i]=__float_as_uint(tf32r(v-h));
    }
}
__device__ __forceinline__ uint4 ldA4(const float* smf,int frag,int lane){
    return *(const uint4*)&smf[(((frag<<5)+lane)<<2)];
}
__device__ __forceinline__ uint2 ldB2(const float* smf,int frag,int lane){
    return *(const uint2*)&smf[(((frag<<5)+lane)<<1)];
}
__device__ __forceinline__ void fillB8(float* smf,int obh,int obl,
        const float* BH,const float* BL,int tid){
    for(int i=tid;i<1024;i+=256){
        ((float4*)(smf+obh))[i]=((const float4*)BH)[i];
        ((float4*)(smf+obl))[i]=((const float4*)BL)[i];
    }
}

// ---------------- prep ------------------------------------------------------------
__global__ void prep_kernel(const int* __restrict__ dst,const int* __restrict__ ety,
        const float* __restrict__ rW,const float* __restrict__ eW,
        const float* __restrict__ Wi,const float* __restrict__ Wh){
    int i=blockIdx.x*blockDim.x+threadIdx.x;
    if(i<EE) atomicAdd(&g_cnt4[dst[i]*4+ety[i]],1);
    if(i<16384){ int k=i>>6,n=i&63; float v=rW[k*64+n];
        int off=(k>>6)*4096+bidx(k&63,n,8);
        float h=tf32r(v); g_BredH[off]=h; g_BredL[off]=tf32r(v-h);
    }else if(i<32768){ int q=i-16384; int k=q>>6,n=q&63;
        float v=eW[(k>>6)*4096+(k&63)*64+n];
        int off=(k>>6)*4096+bidx(k&63,n,8);
        float h=tf32r(v); g_BedgeH[off]=h; g_BedgeL[off]=tf32r(v-h);
    }else if(i<40960){ int q=i-32768; int k=q>>6,n=q&63;
        float v=(k<64)?Wi[n*64+k]:Wh[n*64+k-64];
        int off=(k>>6)*4096+bidx(k&63,n,8);
        float h=tf32r(v); g_BrH[off]=h; g_BrL[off]=tf32r(v-h);
    }else if(i<49152){ int q=i-40960; int k=q>>6,n=q&63;
        float v=(k<64)?Wi[(64+n)*64+k]:Wh[(64+n)*64+k-64];
        int off=(k>>6)*4096+bidx(k&63,n,8);
        float h=tf32r(v); g_BzH[off]=h; g_BzL[off]=tf32r(v-h);
    }else if(i<53248){ int q=i-49152; int k=q>>6,n=q&63;
        float v=Wi[(128+n)*64+k];
        int off=bidx(k,n,8);
        float h=tf32r(v); g_BinH[off]=h; g_BinL[off]=tf32r(v-h);
    }else if(i<57344){ int q=i-53248; int k=q>>6,n=q&63;
        float v=Wh[(128+n)*64+k];
        int off=bidx(k,n,8);
        float h=tf32r(v); g_BhnH[off]=h; g_BhnL[off]=tf32r(v-h);
    }
}
__global__ void scan_kernel(){
    __shared__ int part[1024];
    int tid=threadIdx.x; const int CH=(NN+1023)/1024; int base=tid*CH; int s=0;
    for(int i=0;i<CH;++i){ int n=base+i; if(n<NN) s+=g_cnt4[n*4]+g_cnt4[n*4+1]+g_cnt4[n*4+2]+g_cnt4[n*4+3]; }
    part[tid]=s; __syncthreads();
    for(int off=1;off<1024;off<<=1){ int v=(tid>=off)?part[tid-off]:0; __syncthreads(); part[tid]+=v; __syncthreads(); }
    int run=(tid?part[tid-1]:0);
    for(int i=0;i<CH;++i){ int n=base+i; if(n<NN){ g_rowstart[n]=run; g_cursor[n]=run;
        run+=g_cnt4[n*4]+g_cnt4[n*4+1]+g_cnt4[n*4+2]+g_cnt4[n*4+3]; } }
    if(tid==1023) g_rowstart[NN]=part[1023];
}
__global__ void fill_kernel(const int* __restrict__ src,const int* __restrict__ dst,const int* __restrict__ ety){
    int e=blockIdx.x*blockDim.x+threadIdx.x;
    if(e<EE){ int pos=atomicAdd(&g_cursor[dst[e]],1); g_eidx[pos]=(src[e]<<2)|ety[e]; }
}

// ---------------- reduce: h0 = ann @ reduce_W + rb --------------------------------
#define R_OBH 8192
#define R_OBL 12288
#define SMB_R (16384*4)
__global__ __launch_bounds__(256,2) void reduce_mma(const float* __restrict__ ann,
        const float* __restrict__ rb){
    extern __shared__ float smf[];
    const int tid=threadIdx.x,w=tid>>5,lane=tid&31;
    const int wm=w>>1,wn=w&1,n0=blockIdx.x*128;
    float C[2][4][4]={};
    for(int st=0;st<4;++st){
        for(int idx=tid;idx<2048;idx+=256){
            int row=idx>>4,kq=(idx&15)<<2; int n=n0+row;
            float4 v=make_float4(0,0,0,0);
            if(n<NN) v=*(const float4*)&ann[(size_t)n*256+st*64+kq];
            smf[aidx(row,kq+0,8)]=v.x; smf[aidx(row,kq+1,8)]=v.y;
            smf[aidx(row,kq+2,8)]=v.z; smf[aidx(row,kq+3,8)]=v.w;
        }
        fillB8(smf,R_OBH,R_OBL,g_BredH+st*4096,g_BredL+st*4096,tid);
        __syncthreads();
#pragma unroll
        for(int kc=0;kc<8;++kc){
            uint4 af0=ldA4(smf,(wm*2+0)*8+kc,lane);
            uint4 af1=ldA4(smf,(wm*2+1)*8+kc,lane);
            uint32_t ah0[4],al0[4],ah1[4],al1[4];
            splitR(af0,ah0,al0); splitR(af1,ah1,al1);
            uint2 bh[4],bl[4];
#pragma unroll
            for(int j=0;j<4;++j){
                bh[j]=ldB2(smf+R_OBH,(wn*4+j)*8+kc,lane);
                bl[j]=ldB2(smf+R_OBL,(wn*4+j)*8+kc,lane);
            }
#pragma unroll
            for(int j=0;j<4;++j){ mma8(C[0][j],ah0,(const uint32_t*)&bh[j]);
                                  mma8(C[1][j],ah1,(const uint32_t*)&bh[j]); }
#pragma unroll
            for(int j=0;j<4;++j){ mma8(C[0][j],ah0,(const uint32_t*)&bl[j]);
                                  mma8(C[1][j],ah1,(const uint32_t*)&bl[j]); }
#pragma unroll
            for(int j=0;j<4;++j){ mma8(C[0][j],al0,(const uint32_t*)&bh[j]);
                                  mma8(C[1][j],al1,(const uint32_t*)&bh[j]); }
        }
        __syncthreads();
    }
    const int g=lane>>2,tig=lane&3;
#pragma unroll
    for(int i=0;i<2;++i){
        int base=n0+(wm*2+i)*16+g;
#pragma unroll
        for(int j=0;j<4;++j){
            int col=(wn*4+j)*8+tig*2;
            float b0=rb[col],b1=rb[col+1];
            if(base<NN){ float2 v={C[i][j][0]+b0,C[i][j][1]+b1};
                *(float2*)&g_h0[(size_t)base*64+col]=v; *(float2*)&g_hA[(size_t)base*64+col]=v; }
            if(base+8<NN){ float2 v={C[i][j][2]+b0,C[i][j][3]+b1};
                *(float2*)&g_h0[(size_t)(base+8)*64+col]=v; *(float2*)&g_hA[(size_t)(base+8)*64+col]=v; }
        }
    }
}

// ---------------- fused step: gather + edge mma + GRU -----------------------------
#define S_OBH 16384
#define S_OBL 20480
#define SMB_S (24576*4)
__global__ __launch_bounds__(256,2) void step_mma(
        const float* __restrict__ hin, float* __restrict__ hout,
        const float* __restrict__ eb, const float* __restrict__ bi,
        const float* __restrict__ bh_){
    extern __shared__ float smf[];
    const int tid=threadIdx.x,w=tid>>5,lane=tid&31;
    const int wm=w>>1,wn=w&1,n0=blockIdx.x*64;

    // ---- gather (uniform MLP-8, predicated tail) ----
    for(int i=0;i<8;++i){
        int nloc=w*8+i, n=n0+nloc;
        float2 a0={0,0},a1={0,0},a2={0,0},a3={0,0};
        if(n<NN){
            int e=g_rowstart[n],re=g_rowstart[n+1];
            for(;e<re;e+=8){
                int vv[8]; float2 xx[8];
#pragma unroll
                for(int u=0;u<8;++u){ int idx=(e+u<re)?(e+u):e; vv[u]=g_eidx[idx]; }
#pragma unroll
                for(int u=0;u<8;++u) xx[u]=*(const float2*)&hin[(size_t)(vv[u]>>2)*64+(lane<<1)];
#pragma unroll
                for(int u=0;u<8;++u){
                    if(e+u<re){
                        int t=vv[u]&3;
                        if(t==0){a0.x+=xx[u].x;a0.y+=xx[u].y;}
                        else if(t==1){a1.x+=xx[u].x;a1.y+=xx[u].y;}
                        else if(t==2){a2.x+=xx[u].x;a2.y+=xx[u].y;}
                        else{a3.x+=xx[u].x;a3.y+=xx[u].y;}
                    }
                }
            }
        }
        int k=lane<<1;
        smf[aidx(nloc,k,32)]=a0.x;       smf[aidx(nloc,k+1,32)]=a0.y;
        smf[aidx(nloc,64+k,32)]=a1.x;    smf[aidx(nloc,64+k+1,32)]=a1.y;
        smf[aidx(nloc,128+k,32)]=a2.x;   smf[aidx(nloc,128+k+1,32)]=a2.y;
        smf[aidx(nloc,192+k,32)]=a3.x;   smf[aidx(nloc,192+k+1,32)]=a3.y;
    }

    // ---- edge-type mma: a = sums @ edge_W (interleaved passes) ----
    float C[4][4]={};
    for(int st=0;st<4;++st){
        if(st>0) __syncthreads();
        fillB8(smf,S_OBH,S_OBL,g_BedgeH+st*4096,g_BedgeL+st*4096,tid);
        __syncthreads();
#pragma unroll
        for(int kc=0;kc<8;++kc){
            uint4 af=ldA4(smf,wm*32+st*8+kc,lane);
            uint32_t ah[4],al[4]; splitR(af,ah,al);
            uint2 bh[4],bl[4];
#pragma unroll
            for(int j=0;j<4;++j){
                bh[j]=ldB2(smf+S_OBH,(wn*4+j)*8+kc,lane);
                bl[j]=ldB2(smf+S_OBL,(wn*4+j)*8+kc,lane);
            }
#pragma unroll
            for(int j=0;j<4;++j) mma8(C[j],ah,(const uint32_t*)&bh[j]);
#pragma unroll
            for(int j=0;j<4;++j) mma8(C[j],ah,(const uint32_t*)&bl[j]);
#pragma unroll
            for(int j=0;j<4;++j) mma8(C[j],al,(const uint32_t*)&bh[j]);
        }
    }
    __syncthreads();

    // ---- build gruA = [a | h] (K=128, kcs=16) ----
    const int g=lane>>2,tig=lane&3;
    const int r0loc=wm*16+g, r1loc=r0loc+8;
    const int gr0=n0+r0loc, gr1=n0+r1loc;
    {
        int4 c0=make_int4(0,0,0,0),c1=make_int4(0,0,0,0);
        if(gr0<NN) c0=*(const int4*)&g_cnt4[gr0*4];
        if(gr1<NN) c1=*(const int4*)&g_cnt4[gr1*4];
#pragma unroll
        for(int j=0;j<4;++j){
            int col=(wn*4+j)*8+tig*2;
            float e00=eb[col],e01=eb[col+1],e10=eb[64+col],e11=eb[64+col+1];
            float e20=eb[128+col],e21=eb[128+col+1],e30=eb[192+col],e31=eb[192+col+1];
            smf[aidx(r0loc,col,16)]  =C[j][0]+c0.x*e00+c0.y*e10+c0.z*e20+c0.w*e30;
            smf[aidx(r0loc,col+1,16)]=C[j][1]+c0.x*e01+c0.y*e11+c0.z*e21+c0.w*e31;
            smf[aidx(r1loc,col,16)]  =C[j][2]+c1.x*e00+c1.y*e10+c1.z*e20+c1.w*e30;
            smf[aidx(r1loc,col+1,16)]=C[j][3]+c1.x*e01+c1.y*e11+c1.z*e21+c1.w*e31;
        }
    }
    for(int idx=tid;idx<1024;idx+=256){
        int row=idx>>4,kq=(idx&15)<<2; int n=n0+row;
        float4 v=make_float4(0,0,0,0);
        if(n<NN) v=*(const float4*)&hin[(size_t)n*64+kq];
        smf[aidx(row,64+kq+0,16)]=v.x; smf[aidx(row,64+kq+1,16)]=v.y;
        smf[aidx(row,64+kq+2,16)]=v.z; smf[aidx(row,64+kq+3,16)]=v.w;
    }

    float rv[4][4],tt[4][4],zv[4][4];
#define GATE_MMA(C,BH,BL,NST,AOFF)                                        \
    for(int bst=0;bst<(NST);++bst){                                       \
        __syncthreads();                                                  \
        fillB8(smf,S_OBH,S_OBL,(BH)+bst*4096,(BL)+bst*4096,tid);          \
        __syncthreads();                                                  \
        _Pragma("unroll")                                                 \
        for(int kc=0;kc<8;++kc){                                          \
            uint4 af=ldA4(smf,wm*16+(AOFF)+bst*8+kc,lane);                \
            uint32_t ah[4],al[4]; splitR(af,ah,al);                       \
            uint2 bh[4],bl[4];                                            \
            _Pragma("unroll")                                             \
            for(int j=0;j<4;++j){                                         \
                bh[j]=ldB2(smf+S_OBH,(wn*4+j)*8+kc,lane);                 \
                bl[j]=ldB2(smf+S_OBL,(wn*4+j)*8+kc,lane);                 \
            }                                                             \
            _Pragma("unroll")                                             \
            for(int j=0;j<4;++j) mma8(C[j],ah,(const uint32_t*)&bh[j]);   \
            _Pragma("unroll")                                             \
            for(int j=0;j<4;++j) mma8(C[j],ah,(const uint32_t*)&bl[j]);   \
            _Pragma("unroll")                                             \
            for(int j=0;j<4;++j) mma8(C[j],al,(const uint32_t*)&bh[j]);   \
        }                                                                 \
    }

    { float Cg[4][4]={}; GATE_MMA(Cg,g_BrH,g_BrL,2,0)
#pragma unroll
      for(int j=0;j<4;++j)
#pragma unroll
        for(int q=0;q<4;++q){ int col=(wn*4+j)*8+tig*2+(q&1);
            rv[j][q]=1.f/(1.f+expf(-(Cg[j][q]+bi[col]+bh_[col]))); } }
    { float Cg[4][4]={}; GATE_MMA(Cg,g_BhnH,g_BhnL,1,8)
#pragma unroll
      for(int j=0;j<4;++j)
#pragma unroll
        for(int q=0;q<4;++q){ int col=(wn*4+j)*8+tig*2+(q&1);
            tt[j][q]=rv[j][q]*(Cg[j][q]+bh_[128+col]); } }
    { float Cg[4][4]={}; GATE_MMA(Cg,g_BzH,g_BzL,2,0)
#pragma unroll
      for(int j=0;j<4;++j)
#pragma unroll
        for(int q=0;q<4;++q){ int col=(wn*4+j)*8+tig*2+(q&1);
            zv[j][q]=1.f/(1.f+expf(-(Cg[j][q]+bi[64+col]+bh_[64+col]))); } }
    { float Cg[4][4]={}; GATE_MMA(Cg,g_BinH,g_BinL,1,0)
#pragma unroll
      for(int j=0;j<4;++j){
          int col=(wn*4+j)*8+tig*2;
          if(gr0<NN){
              float h0v=smf[aidx(r0loc,64+col,16)];
              float h1v=smf[aidx(r0loc,64+col+1,16)];
              float n0v=tanhf(Cg[j][0]+bi[128+col]+tt[j][0]);
              float n1v=tanhf(Cg[j][1]+bi[128+col+1]+tt[j][1]);
              float2 hn={(1.f-zv[j][0])*n0v+zv[j][0]*h0v,(1.f-zv[j][1])*n1v+zv[j][1]*h1v};
              *(float2*)&hout[(size_t)gr0*64+col]=hn;
          }
          if(gr1<NN){
              float h0v=smf[aidx(r1loc,64+col,16)];
              float h1v=smf[aidx(r1loc,64+col+1,16)];
              float n0v=tanhf(Cg[j][2]+bi[128+col]+tt[j][2]);
              float n1v=tanhf(Cg[j][3]+bi[128+col+1]+tt[j][3]);
              float2 hn={(1.f-zv[j][2])*n0v+zv[j][2]*h0v,(1.f-zv[j][3])*n1v+zv[j][3]*h1v};
              *(float2*)&hout[(size_t)gr1*64+col]=hn;
          } } }
#undef GATE_MMA
}

// ---------------- attention pooling -------------------------------------------------
__device__ void atomicMaxFloat(float* addr,float v){
    int* ia=(int*)addr; int old=*ia;
    while(true){ float f=__int_as_float(old); if(f>=v) break;
        int as=old; old=atomicCAS(ia,as,__float_as_int(v)); if(old==as) break; }
}
__global__ __launch_bounds__(256) void gate_kernel(const int* __restrict__ gid,
        const float* __restrict__ gW,const float* __restrict__ gb){
    int gt=blockIdx.x*blockDim.x+threadIdx.x; int n=gt>>5; if(n>=NN) return;
    int lane=gt&31,j0=lane<<2;
    float4 fv=(j0<64)?*(const float4*)&g_hA[(size_t)n*64+j0]:*(const float4*)&g_h0[(size_t)n*64+j0-64];
    float4 wv=*(const float4*)&gW[j0];
    float s=fv.x*wv.x+fv.y*wv.y+fv.z*wv.z+fv.w*wv.w;
#pragma unroll
    for(int o=16;o;o>>=1) s+=__shfl_xor_sync(0xffffffffu,s,o);
    if(lane==0){ float g=s+gb[0]; g_gate[n]=g; atomicMaxFloat(&g_gmax[gid[n]],g); }
}
__global__ __launch_bounds__(256) void pool_kernel(const int* __restrict__ gid){
    int gt=blockIdx.x*blockDim.x+threadIdx.x; int n=gt>>5; if(n>=NN) return;
    int lane=gt&31; int g=gid[n];
    float gm=g_gmax[g]; if(!isfinite(gm)) gm=0.f;
    float e=expf(g_gate[n]-gm);
    int j0=lane<<2;
    float4 fv=(j0<64)?*(const float4*)&g_hA[(size_t)n*64+j0]:*(const float4*)&g_h0[(size_t)n*64+j0-64];
    float* rp=&g_rsum[g*128+j0];
    atomicAdd(rp,e*fv.x); atomicAdd(rp+1,e*fv.y); atomicAdd(rp+2,e*fv.z); atomicAdd(rp+3,e*fv.w);
    if(lane==0) atomicAdd(&g_den[g],e);
}
__global__ void out_kernel(const float* __restrict__ oW,const float* __restrict__ ob,float* __restrict__ out){
    int b=blockIdx.x,tid=threadIdx.x;
    float dn=g_den[b]; float inv=(dn>0.f)?(1.f/dn):0.f;
    float r=g_rsum[b*128+tid]*inv;
    float p0=r*oW[tid*2],p1=r*oW[tid*2+1];
#pragma unroll
    for(int o=16;o;o>>=1){ p0+=__shfl_xor_sync(0xffffffffu,p0,o); p1+=__shfl_xor_sync(0xffffffffu,p1,o); }
    __shared__ float s0[4],s1[4];
    if((tid&31)==0){ s0[tid>>5]=p0; s1[tid>>5]=p1; }
    __syncthreads();
    if(tid==0){ out[b*2]=s0[0]+s0[1]+s0[2]+s0[3]+ob[0]; out[b*2+1]=s1[0]+s1[1]+s1[2]+s1[3]+ob[1]; }
}
__global__ void tail_zero(){
    int i=blockIdx.x*blockDim.x+threadIdx.x;
    if(i<NN*4) g_cnt4[i]=0;
    if(i<BB*128) g_rsum[i]=0.f;
    if(i<BB){ g_den[i]=0.f; g_gmax[i]=__int_as_float(0xff800000); }
}

// ---------------- host orchestration -------------------------------------------------
extern "C" void kernel_launch(void* const* d_in,const int* in_sizes,int n_in,
                              void* d_out,int out_size){
    const float* ann=(const float*)d_in[0];
    const int* src=(const int*)d_in[1];
    const int* dst=(const int*)d_in[2];
    const int* ety=(const int*)d_in[3];
    const int* gid=(const int*)d_in[4];
    const float* reduce_W=(const float*)d_in[5];
    const float* reduce_b=(const float*)d_in[6];
    const float* edge_W=(const float*)d_in[7];
    const float* edge_b=(const float*)d_in[8];
    const float* gru_Wi=(const float*)d_in[9];
    const float* gru_bi=(const float*)d_in[10];
    const float* gru_Wh=(const float*)d_in[11];
    const float* gru_bh=(const float*)d_in[12];
    const float* gate_W=(const float*)d_in[13];
    const float* gate_b=(const float*)d_in[14];
    const float* out_W=(const float*)d_in[15];
    const float* out_b=(const float*)d_in[16];
    float* out=(float*)d_out;

    float *hA,*hB;
    cudaGetSymbolAddress((void**)&hA,g_hA);
    cudaGetSymbolAddress((void**)&hB,g_hB);

    cudaFuncSetAttribute(reduce_mma,cudaFuncAttributeMaxDynamicSharedMemorySize,SMB_R);
    cudaFuncSetAttribute(step_mma,cudaFuncAttributeMaxDynamicSharedMemorySize,SMB_S);

    prep_kernel<<<(EE+255)/256,256>>>(dst,ety,reduce_W,edge_W,gru_Wi,gru_Wh);
    scan_kernel<<<1,1024>>>();
    fill_kernel<<<(EE+255)/256,256>>>(src,dst,ety);
    reduce_mma<<<GRID128,256,SMB_R>>>(ann,reduce_b);   // launch #4 -> profiled
    for(int s=0;s<NSTEPS;++s){
        const float* hin=(s&1)?hB:hA;
        float* hout=(s&1)?hA:hB;
        step_mma<<<GRID64,256,SMB_S>>>(hin,hout,edge_b,gru_bi,gru_bh);
    }
    gate_kernel<<<(NN*32+255)/256,256>>>(gid,gate_W,gate_b);
    pool_kernel<<<(NN*32+255)/256,256>>>(gid);
    out_kernel<<<BB,128>>>(out_W,out_b,out);
    tail_zero<<<(NN*4+255)/256,256>>>();
}

// round 13
// speedup vs baseline: 1.6678x; 1.1254x over previous
#include <cuda_runtime.h>
#include <math.h>
#include <stdint.h>

#define NN 100000
#define EE 1200000
#define BB 64
#define NSTEPS 6
#define GRID128 782
#define GRID64  1563

__device__ float g_hA[NN * 64];
__device__ float g_hB[NN * 64];
__device__ float g_h0[NN * 64];
__device__ int   g_rowstart[NN + 1];
__device__ int   g_cursor[NN];
__device__ int   g_eidx[EE];
__device__ int   g_cnt4[NN * 4];
__device__ float g_gate[NN];
__device__ float g_gmax[BB];
__device__ float g_den[BB];
__device__ float g_rsum[BB * 128];
__device__ float g_BredH[16384],g_BredL[16384];
__device__ float g_BedgeH[16384],g_BedgeL[16384];
__device__ float g_BrH[8192],g_BrL[8192];
__device__ float g_BzH[8192],g_BzL[8192];
__device__ float g_BinH[4096],g_BinL[4096];
__device__ float g_BhnH[4096],g_BhnL[4096];

__device__ __forceinline__ float tf32r(float x){ float y; asm("cvt.rna.tf32.f32 %0,%1;":"=f"(y):"f"(x)); return y; }

__device__ __forceinline__ int aidx(int row,int k,int kcs){
    int mt=row>>4, r=row&15;
    return (((mt*kcs+(k>>3))<<5) + (((r&7)<<2)+(k&3)))*4 + ((r>>3)+(((k>>2)&1)<<1));
}
__device__ __forceinline__ int bidx(int k,int n,int kcs){
    return ((((n>>3)*kcs+(k>>3))<<5) + (((n&7)<<2)+(k&3)))*2 + ((k>>2)&1);
}
__device__ __forceinline__ void mma8(float* c,const uint32_t* a,const uint32_t* b){
    asm volatile("mma.sync.aligned.m16n8k8.row.col.f32.tf32.tf32.f32 "
        "{%0,%1,%2,%3},{%4,%5,%6,%7},{%8,%9},{%0,%1,%2,%3};"
        : "+f"(c[0]),"+f"(c[1]),"+f"(c[2]),"+f"(c[3])
        : "r"(a[0]),"r"(a[1]),"r"(a[2]),"r"(a[3]),"r"(b[0]),"r"(b[1]));
}
__device__ __forceinline__ void splitR(uint4 a,uint32_t* ah,uint32_t* al){
    const uint32_t* p=(const uint32_t*)&a;
#pragma unroll
    for(int i=0;i<4;++i){
        float v=__uint_as_float(p[i]); float h=tf32r(v);
        ah[i]=__float_as_uint(h); al[i]=__float_as_uint(tf32r(v-h));
    }
}
__device__ __forceinline__ uint4 ldA4(const float* smf,int frag,int lane){
    return *(const uint4*)&smf[(((frag<<5)+lane)<<2)];
}
// B fragment straight from global (L1/L2-resident pre-split tiles)
__device__ __forceinline__ uint2 ldBg(const float* __restrict__ B,int frag,int lane){
    return *(const uint2*)&B[(((frag<<5)+lane)<<1)];
}

// ---------------- prep ------------------------------------------------------------
__global__ void prep_kernel(const int* __restrict__ dst,const int* __restrict__ ety,
        const float* __restrict__ rW,const float* __restrict__ eW,
        const float* __restrict__ Wi,const float* __restrict__ Wh){
    int i=blockIdx.x*blockDim.x+threadIdx.x;
    if(i<EE) atomicAdd(&g_cnt4[dst[i]*4+ety[i]],1);
    if(i<16384){ int k=i>>6,n=i&63; float v=rW[k*64+n];
        int off=(k>>6)*4096+bidx(k&63,n,8);
        float h=tf32r(v); g_BredH[off]=h; g_BredL[off]=tf32r(v-h);
    }else if(i<32768){ int q=i-16384; int k=q>>6,n=q&63;
        float v=eW[(k>>6)*4096+(k&63)*64+n];
        int off=(k>>6)*4096+bidx(k&63,n,8);
        float h=tf32r(v); g_BedgeH[off]=h; g_BedgeL[off]=tf32r(v-h);
    }else if(i<40960){ int q=i-32768; int k=q>>6,n=q&63;
        float v=(k<64)?Wi[n*64+k]:Wh[n*64+k-64];
        int off=(k>>6)*4096+bidx(k&63,n,8);
        float h=tf32r(v); g_BrH[off]=h; g_BrL[off]=tf32r(v-h);
    }else if(i<49152){ int q=i-40960; int k=q>>6,n=q&63;
        float v=(k<64)?Wi[(64+n)*64+k]:Wh[(64+n)*64+k-64];
        int off=(k>>6)*4096+bidx(k&63,n,8);
        float h=tf32r(v); g_BzH[off]=h; g_BzL[off]=tf32r(v-h);
    }else if(i<53248){ int q=i-49152; int k=q>>6,n=q&63;
        float v=Wi[(128+n)*64+k];
        int off=bidx(k,n,8);
        float h=tf32r(v); g_BinH[off]=h; g_BinL[off]=tf32r(v-h);
    }else if(i<57344){ int q=i-53248; int k=q>>6,n=q&63;
        float v=Wh[(128+n)*64+k];
        int off=bidx(k,n,8);
        float h=tf32r(v); g_BhnH[off]=h; g_BhnL[off]=tf32r(v-h);
    }
}
__global__ void scan_kernel(){
    __shared__ int part[1024];
    int tid=threadIdx.x; const int CH=(NN+1023)/1024; int base=tid*CH; int s=0;
    for(int i=0;i<CH;++i){ int n=base+i; if(n<NN) s+=g_cnt4[n*4]+g_cnt4[n*4+1]+g_cnt4[n*4+2]+g_cnt4[n*4+3]; }
    part[tid]=s; __syncthreads();
    for(int off=1;off<1024;off<<=1){ int v=(tid>=off)?part[tid-off]:0; __syncthreads(); part[tid]+=v; __syncthreads(); }
    int run=(tid?part[tid-1]:0);
    for(int i=0;i<CH;++i){ int n=base+i; if(n<NN){ g_rowstart[n]=run; g_cursor[n]=run;
        run+=g_cnt4[n*4]+g_cnt4[n*4+1]+g_cnt4[n*4+2]+g_cnt4[n*4+3]; } }
    if(tid==1023) g_rowstart[NN]=part[1023];
}
__global__ void fill_kernel(const int* __restrict__ src,const int* __restrict__ dst,const int* __restrict__ ety){
    int e=blockIdx.x*blockDim.x+threadIdx.x;
    if(e<EE){ int pos=atomicAdd(&g_cursor[dst[e]],1); g_eidx[pos]=(src[e]<<2)|ety[e]; }
}

// ---------------- reduce: h0 = ann @ reduce_W + rb --------------------------------
// smem: A only, 8192 floats (32 KB); B from global
#define SMB_R (8192*4)
__global__ __launch_bounds__(256,3) void reduce_mma(const float* __restrict__ ann,
        const float* __restrict__ rb){
    extern __shared__ float smf[];
    const int tid=threadIdx.x,w=tid>>5,lane=tid&31;
    const int wm=w>>1,wn=w&1,n0=blockIdx.x*128;
    float C[2][4][4]={};
    for(int st=0;st<4;++st){
        if(st>0) __syncthreads();
        for(int idx=tid;idx<2048;idx+=256){
            int row=idx>>4,kq=(idx&15)<<2; int n=n0+row;
            float4 v=make_float4(0,0,0,0);
            if(n<NN) v=*(const float4*)&ann[(size_t)n*256+st*64+kq];
            smf[aidx(row,kq+0,8)]=v.x; smf[aidx(row,kq+1,8)]=v.y;
            smf[aidx(row,kq+2,8)]=v.z; smf[aidx(row,kq+3,8)]=v.w;
        }
        __syncthreads();
        const float* BH=g_BredH+st*4096;
        const float* BL=g_BredL+st*4096;
#pragma unroll
        for(int kc=0;kc<8;++kc){
            uint4 af0=ldA4(smf,(wm*2+0)*8+kc,lane);
            uint4 af1=ldA4(smf,(wm*2+1)*8+kc,lane);
            uint32_t ah0[4],al0[4],ah1[4],al1[4];
            splitR(af0,ah0,al0); splitR(af1,ah1,al1);
            uint2 bh[4],bl[4];
#pragma unroll
            for(int j=0;j<4;++j){
                bh[j]=ldBg(BH,(wn*4+j)*8+kc,lane);
                bl[j]=ldBg(BL,(wn*4+j)*8+kc,lane);
            }
#pragma unroll
            for(int j=0;j<4;++j){ mma8(C[0][j],ah0,(const uint32_t*)&bh[j]);
                                  mma8(C[1][j],ah1,(const uint32_t*)&bh[j]); }
#pragma unroll
            for(int j=0;j<4;++j){ mma8(C[0][j],ah0,(const uint32_t*)&bl[j]);
                                  mma8(C[1][j],ah1,(const uint32_t*)&bl[j]); }
#pragma unroll
            for(int j=0;j<4;++j){ mma8(C[0][j],al0,(const uint32_t*)&bh[j]);
                                  mma8(C[1][j],al1,(const uint32_t*)&bh[j]); }
        }
    }
    const int g=lane>>2,tig=lane&3;
#pragma unroll
    for(int i=0;i<2;++i){
        int base=n0+(wm*2+i)*16+g;
#pragma unroll
        for(int j=0;j<4;++j){
            int col=(wn*4+j)*8+tig*2;
            float b0=rb[col],b1=rb[col+1];
            if(base<NN){ float2 v={C[i][j][0]+b0,C[i][j][1]+b1};
                *(float2*)&g_h0[(size_t)base*64+col]=v; *(float2*)&g_hA[(size_t)base*64+col]=v; }
            if(base+8<NN){ float2 v={C[i][j][2]+b0,C[i][j][3]+b1};
                *(float2*)&g_h0[(size_t)(base+8)*64+col]=v; *(float2*)&g_hA[(size_t)(base+8)*64+col]=v; }
        }
    }
}

// ---------------- fused step: gather + edge mma + GRU -----------------------------
// smem: A only, 16384 floats (64 KB); B from global
#define SMB_S (16384*4)
__global__ __launch_bounds__(256,3) void step_mma(
        const float* __restrict__ hin, float* __restrict__ hout,
        const float* __restrict__ eb, const float* __restrict__ bi,
        const float* __restrict__ bh_){
    extern __shared__ float smf[];
    const int tid=threadIdx.x,w=tid>>5,lane=tid&31;
    const int wm=w>>1,wn=w&1,n0=blockIdx.x*64;

    // ---- gather (uniform MLP-8, predicated tail) into aggA (kcs=32) ----
    for(int i=0;i<8;++i){
        int nloc=w*8+i, n=n0+nloc;
        float2 a0={0,0},a1={0,0},a2={0,0},a3={0,0};
        if(n<NN){
            int e=g_rowstart[n],re=g_rowstart[n+1];
            for(;e<re;e+=8){
                int vv[8]; float2 xx[8];
#pragma unroll
                for(int u=0;u<8;++u){ int idx=(e+u<re)?(e+u):e; vv[u]=g_eidx[idx]; }
#pragma unroll
                for(int u=0;u<8;++u) xx[u]=*(const float2*)&hin[(size_t)(vv[u]>>2)*64+(lane<<1)];
#pragma unroll
                for(int u=0;u<8;++u){
                    if(e+u<re){
                        int t=vv[u]&3;
                        if(t==0){a0.x+=xx[u].x;a0.y+=xx[u].y;}
                        else if(t==1){a1.x+=xx[u].x;a1.y+=xx[u].y;}
                        else if(t==2){a2.x+=xx[u].x;a2.y+=xx[u].y;}
                        else{a3.x+=xx[u].x;a3.y+=xx[u].y;}
                    }
                }
            }
        }
        int k=lane<<1;
        smf[aidx(nloc,k,32)]=a0.x;       smf[aidx(nloc,k+1,32)]=a0.y;
        smf[aidx(nloc,64+k,32)]=a1.x;    smf[aidx(nloc,64+k+1,32)]=a1.y;
        smf[aidx(nloc,128+k,32)]=a2.x;   smf[aidx(nloc,128+k+1,32)]=a2.y;
        smf[aidx(nloc,192+k,32)]=a3.x;   smf[aidx(nloc,192+k+1,32)]=a3.y;
    }
    __syncthreads();

    // ---- edge-type mma over 4 B stages, no barriers (B from global) ----
    float C[4][4]={};
#pragma unroll
    for(int st=0;st<4;++st){
        const float* BH=g_BedgeH+st*4096;
        const float* BL=g_BedgeL+st*4096;
#pragma unroll
        for(int kc=0;kc<8;++kc){
            uint4 af=ldA4(smf,wm*32+st*8+kc,lane);
            uint32_t ah[4],al[4]; splitR(af,ah,al);
            uint2 bh[4],bl[4];
#pragma unroll
            for(int j=0;j<4;++j){
                bh[j]=ldBg(BH,(wn*4+j)*8+kc,lane);
                bl[j]=ldBg(BL,(wn*4+j)*8+kc,lane);
            }
#pragma unroll
            for(int j=0;j<4;++j) mma8(C[j],ah,(const uint32_t*)&bh[j]);
#pragma unroll
            for(int j=0;j<4;++j) mma8(C[j],ah,(const uint32_t*)&bl[j]);
#pragma unroll
            for(int j=0;j<4;++j) mma8(C[j],al,(const uint32_t*)&bh[j]);
        }
    }
    __syncthreads();   // all warps done reading aggA before overwrite

    // ---- build gruA = [a | h] (kcs=16) ----
    const int g=lane>>2,tig=lane&3;
    const int r0loc=wm*16+g, r1loc=r0loc+8;
    const int gr0=n0+r0loc, gr1=n0+r1loc;
    {
        int4 c0=make_int4(0,0,0,0),c1=make_int4(0,0,0,0);
        if(gr0<NN) c0=*(const int4*)&g_cnt4[gr0*4];
        if(gr1<NN) c1=*(const int4*)&g_cnt4[gr1*4];
#pragma unroll
        for(int j=0;j<4;++j){
            int col=(wn*4+j)*8+tig*2;
            float e00=eb[col],e01=eb[col+1],e10=eb[64+col],e11=eb[64+col+1];
            float e20=eb[128+col],e21=eb[128+col+1],e30=eb[192+col],e31=eb[192+col+1];
            smf[aidx(r0loc,col,16)]  =C[j][0]+c0.x*e00+c0.y*e10+c0.z*e20+c0.w*e30;
            smf[aidx(r0loc,col+1,16)]=C[j][1]+c0.x*e01+c0.y*e11+c0.z*e21+c0.w*e31;
            smf[aidx(r1loc,col,16)]  =C[j][2]+c1.x*e00+c1.y*e10+c1.z*e20+c1.w*e30;
            smf[aidx(r1loc,col+1,16)]=C[j][3]+c1.x*e01+c1.y*e11+c1.z*e21+c1.w*e31;
        }
    }
    for(int idx=tid;idx<1024;idx+=256){
        int row=idx>>4,kq=(idx&15)<<2; int n=n0+row;
        float4 v=make_float4(0,0,0,0);
        if(n<NN) v=*(const float4*)&hin[(size_t)n*64+kq];
        smf[aidx(row,64+kq+0,16)]=v.x; smf[aidx(row,64+kq+1,16)]=v.y;
        smf[aidx(row,64+kq+2,16)]=v.z; smf[aidx(row,64+kq+3,16)]=v.w;
    }
    __syncthreads();

    // ---- 4 gates, zero barriers ----
    float rv[4][4],tt[4][4],zv[4][4];
#define GATE_MMA(C,BHA,BLA,NST,AOFF)                                      \
    for(int bst=0;bst<(NST);++bst){                                       \
        const float* BH=(BHA)+bst*4096;                                   \
        const float* BL=(BLA)+bst*4096;                                   \
        _Pragma("unroll")                                                 \
        for(int kc=0;kc<8;++kc){                                          \
            uint4 af=ldA4(smf,wm*16+(AOFF)+bst*8+kc,lane);                \
            uint32_t ah[4],al[4]; splitR(af,ah,al);                       \
            uint2 bh[4],bl[4];                                            \
            _Pragma("unroll")                                             \
            for(int j=0;j<4;++j){                                         \
                bh[j]=ldBg(BH,(wn*4+j)*8+kc,lane);                        \
                bl[j]=ldBg(BL,(wn*4+j)*8+kc,lane);                        \
            }                                                             \
            _Pragma("unroll")                                             \
            for(int j=0;j<4;++j) mma8(C[j],ah,(const uint32_t*)&bh[j]);   \
            _Pragma("unroll")                                             \
            for(int j=0;j<4;++j) mma8(C[j],ah,(const uint32_t*)&bl[j]);   \
            _Pragma("unroll")                                             \
            for(int j=0;j<4;++j) mma8(C[j],al,(const uint32_t*)&bh[j]);   \
        }                                                                 \
    }

    { float Cg[4][4]={}; GATE_MMA(Cg,g_BrH,g_BrL,2,0)
#pragma unroll
      for(int j=0;j<4;++j)
#pragma unroll
        for(int q=0;q<4;++q){ int col=(wn*4+j)*8+tig*2+(q&1);
            rv[j][q]=1.f/(1.f+expf(-(Cg[j][q]+bi[col]+bh_[col]))); } }
    { float Cg[4][4]={}; GATE_MMA(Cg,g_BhnH,g_BhnL,1,8)
#pragma unroll
      for(int j=0;j<4;++j)
#pragma unroll
        for(int q=0;q<4;++q){ int col=(wn*4+j)*8+tig*2+(q&1);
            tt[j][q]=rv[j][q]*(Cg[j][q]+bh_[128+col]); } }
    { float Cg[4][4]={}; GATE_MMA(Cg,g_BzH,g_BzL,2,0)
#pragma unroll
      for(int j=0;j<4;++j)
#pragma unroll
        for(int q=0;q<4;++q){ int col=(wn*4+j)*8+tig*2+(q&1);
            zv[j][q]=1.f/(1.f+expf(-(Cg[j][q]+bi[64+col]+bh_[64+col]))); } }
    { float Cg[4][4]={}; GATE_MMA(Cg,g_BinH,g_BinL,1,0)
#pragma unroll
      for(int j=0;j<4;++j){
          int col=(wn*4+j)*8+tig*2;
          if(gr0<NN){
              float h0v=smf[aidx(r0loc,64+col,16)];
              float h1v=smf[aidx(r0loc,64+col+1,16)];
              float n0v=tanhf(Cg[j][0]+bi[128+col]+tt[j][0]);
              float n1v=tanhf(Cg[j][1]+bi[128+col+1]+tt[j][1]);
              float2 hn={(1.f-zv[j][0])*n0v+zv[j][0]*h0v,(1.f-zv[j][1])*n1v+zv[j][1]*h1v};
              *(float2*)&hout[(size_t)gr0*64+col]=hn;
          }
          if(gr1<NN){
              float h0v=smf[aidx(r1loc,64+col,16)];
              float h1v=smf[aidx(r1loc,64+col+1,16)];
              float n0v=tanhf(Cg[j][2]+bi[128+col]+tt[j][2]);
              float n1v=tanhf(Cg[j][3]+bi[128+col+1]+tt[j][3]);
              float2 hn={(1.f-zv[j][2])*n0v+zv[j][2]*h0v,(1.f-zv[j][3])*n1v+zv[j][3]*h1v};
              *(float2*)&hout[(size_t)gr1*64+col]=hn;
          } } }
#undef GATE_MMA
}

// ---------------- attention pooling -------------------------------------------------
__device__ void atomicMaxFloat(float* addr,float v){
    int* ia=(int*)addr; int old=*ia;
    while(true){ float f=__int_as_float(old); if(f>=v) break;
        int as=old; old=atomicCAS(ia,as,__float_as_int(v)); if(old==as) break; }
}
__global__ __launch_bounds__(256) void gate_kernel(const int* __restrict__ gid,
        const float* __restrict__ gW,const float* __restrict__ gb){
    int gt=blockIdx.x*blockDim.x+threadIdx.x; int n=gt>>5; if(n>=NN) return;
    int lane=gt&31,j0=lane<<2;
    float4 fv=(j0<64)?*(const float4*)&g_hA[(size_t)n*64+j0]:*(const float4*)&g_h0[(size_t)n*64+j0-64];
    float4 wv=*(const float4*)&gW[j0];
    float s=fv.x*wv.x+fv.y*wv.y+fv.z*wv.z+fv.w*wv.w;
#pragma unroll
    for(int o=16;o;o>>=1) s+=__shfl_xor_sync(0xffffffffu,s,o);
    if(lane==0){ float g=s+gb[0]; g_gate[n]=g; atomicMaxFloat(&g_gmax[gid[n]],g); }
}
__global__ __launch_bounds__(256) void pool_kernel(const int* __restrict__ gid){
    int gt=blockIdx.x*blockDim.x+threadIdx.x; int n=gt>>5; if(n>=NN) return;
    int lane=gt&31; int g=gid[n];
    float gm=g_gmax[g]; if(!isfinite(gm)) gm=0.f;
    float e=expf(g_gate[n]-gm);
    int j0=lane<<2;
    float4 fv=(j0<64)?*(const float4*)&g_hA[(size_t)n*64+j0]:*(const float4*)&g_h0[(size_t)n*64+j0-64];
    float* rp=&g_rsum[g*128+j0];
    atomicAdd(rp,e*fv.x); atomicAdd(rp+1,e*fv.y); atomicAdd(rp+2,e*fv.z); atomicAdd(rp+3,e*fv.w);
    if(lane==0) atomicAdd(&g_den[g],e);
}
__global__ void out_kernel(const float* __restrict__ oW,const float* __restrict__ ob,float* __restrict__ out){
    int b=blockIdx.x,tid=threadIdx.x;
    float dn=g_den[b]; float inv=(dn>0.f)?(1.f/dn):0.f;
    float r=g_rsum[b*128+tid]*inv;
    float p0=r*oW[tid*2],p1=r*oW[tid*2+1];
#pragma unroll
    for(int o=16;o;o>>=1){ p0+=__shfl_xor_sync(0xffffffffu,p0,o); p1+=__shfl_xor_sync(0xffffffffu,p1,o); }
    __shared__ float s0[4],s1[4];
    if((tid&31)==0){ s0[tid>>5]=p0; s1[tid>>5]=p1; }
    __syncthreads();
    if(tid==0){ out[b*2]=s0[0]+s0[1]+s0[2]+s0[3]+ob[0]; out[b*2+1]=s1[0]+s1[1]+s1[2]+s1[3]+ob[1]; }
}
__global__ void tail_zero(){
    int i=blockIdx.x*blockDim.x+threadIdx.x;
    if(i<NN*4) g_cnt4[i]=0;
    if(i<BB*128) g_rsum[i]=0.f;
    if(i<BB){ g_den[i]=0.f; g_gmax[i]=__int_as_float(0xff800000); }
}

// ---------------- host orchestration -------------------------------------------------
extern "C" void kernel_launch(void* const* d_in,const int* in_sizes,int n_in,
                              void* d_out,int out_size){
    const float* ann=(const float*)d_in[0];
    const int* src=(const int*)d_in[1];
    const int* dst=(const int*)d_in[2];
    const int* ety=(const int*)d_in[3];
    const int* gid=(const int*)d_in[4];
    const float* reduce_W=(const float*)d_in[5];
    const float* reduce_b=(const float*)d_in[6];
    const float* edge_W=(const float*)d_in[7];
    const float* edge_b=(const float*)d_in[8];
    const float* gru_Wi=(const float*)d_in[9];
    const float* gru_bi=(const float*)d_in[10];
    const float* gru_Wh=(const float*)d_in[11];
    const float* gru_bh=(const float*)d_in[12];
    const float* gate_W=(const float*)d_in[13];
    const float* gate_b=(const float*)d_in[14];
    const float* out_W=(const float*)d_in[15];
    const float* out_b=(const float*)d_in[16];
    float* out=(float*)d_out;

    float *hA,*hB;
    cudaGetSymbolAddress((void**)&hA,g_hA);
    cudaGetSymbolAddress((void**)&hB,g_hB);

    cudaFuncSetAttribute(reduce_mma,cudaFuncAttributeMaxDynamicSharedMemorySize,SMB_R);
    cudaFuncSetAttribute(step_mma,cudaFuncAttributeMaxDynamicSharedMemorySize,SMB_S);

    prep_kernel<<<(EE+255)/256,256>>>(dst,ety,reduce_W,edge_W,gru_Wi,gru_Wh);
    scan_kernel<<<1,1024>>>();
    fill_kernel<<<(EE+255)/256,256>>>(src,dst,ety);
    reduce_mma<<<GRID128,256,SMB_R>>>(ann,reduce_b);   // launch #4 -> profiled
    for(int s=0;s<NSTEPS;++s){
        const float* hin=(s&1)?hB:hA;
        float* hout=(s&1)?hA:hB;
        step_mma<<<GRID64,256,SMB_S>>>(hin,hout,edge_b,gru_bi,gru_bh);
    }
    gate_kernel<<<(NN*32+255)/256,256>>>(gid,gate_W,gate_b);
    pool_kernel<<<(NN*32+255)/256,256>>>(gid);
    out_kernel<<<BB,128>>>(out_W,out_b,out);
    tail_zero<<<(NN*4+255)/256,256>>>();
}

// round 14
// speedup vs baseline: 1.9708x; 1.1817x over previous
#include <cuda_runtime.h>
#include <cuda_bf16.h>
#include <math.h>
#include <stdint.h>

#define NN 100000
#define EE 1200000
#define BB 64
#define NSTEPS 6
#define GRID128 782
#define GRID64  1563

__device__ float g_hA[NN * 64];
__device__ float g_hB[NN * 64];
__device__ float g_h0[NN * 64];
__device__ int   g_rowstart[NN + 1];
__device__ int   g_cursor[NN];
__device__ int   g_eidx[EE];
__device__ int   g_cnt4[NN * 4];
__device__ float g_gate[NN];
__device__ float g_gmax[BB];
__device__ float g_den[BB];
__device__ float g_rsum[BB * 128];
// pre-split packed-bf16x2 fragment-permuted B tiles (u32 units)
__device__ uint32_t g_BredH[8192],g_BredL[8192];    // 4 stages of 64-K (2048 u32 each)
__device__ uint32_t g_BedgeH[8192],g_BedgeL[8192];  // 4 type-stages
__device__ uint32_t g_BrH[4096],g_BrL[4096];        // K=128, kct=8
__device__ uint32_t g_BzH[4096],g_BzL[4096];
__device__ uint32_t g_BinH[2048],g_BinL[2048];      // K=64, kct=4
__device__ uint32_t g_BhnH[2048],g_BhnL[2048];

// ---- bf16 pack/split helpers ----
__device__ __forceinline__ uint32_t bfpack(float v0,float v1){
    __nv_bfloat162 t=__floats2bfloat162_rn(v0,v1);
    return *(uint32_t*)&t;
}
__device__ __forceinline__ void split2pack(float v0,float v1,uint32_t&hi,uint32_t&lo){
    float h0=__bfloat162float(__float2bfloat16(v0));
    float h1=__bfloat162float(__float2bfloat16(v1));
    hi=bfpack(h0,h1); lo=bfpack(v0-h0,v1-h1);
}
__device__ __forceinline__ float2 unsplit(uint32_t hi,uint32_t lo){
    __nv_bfloat162 h=*(__nv_bfloat162*)&hi,l=*(__nv_bfloat162*)&lo;
    return make_float2(__bfloat162float(h.x)+__bfloat162float(l.x),
                       __bfloat162float(h.y)+__bfloat162float(l.y));
}

// fragment-permuted u32 indices for m16n8k16 bf16 frags
// A frag (16 rows x 16 k) = 128 u32; B frag (16 k x 8 n) = 64 u32
__device__ __forceinline__ int aidx16(int row,int k,int kct){
    int frag=(row>>4)*kct+(k>>4);
    return frag*128+(((row&7)<<2)+((k&7)>>1))*4+((row>>3)&1)+(((k>>3)&1)<<1);
}
__device__ __forceinline__ int bidx16(int k,int n,int kct){
    int frag=(n>>3)*kct+(k>>4);
    return frag*64+(((n&7)<<2)+((k&7)>>1))*2+((k>>3)&1);
}
__device__ __forceinline__ void mma16(float* c,const uint32_t* a,const uint32_t* b){
    asm volatile("mma.sync.aligned.m16n8k16.row.col.f32.bf16.bf16.f32 "
        "{%0,%1,%2,%3},{%4,%5,%6,%7},{%8,%9},{%0,%1,%2,%3};"
        : "+f"(c[0]),"+f"(c[1]),"+f"(c[2]),"+f"(c[3])
        : "r"(a[0]),"r"(a[1]),"r"(a[2]),"r"(a[3]),"r"(b[0]),"r"(b[1]));
}
__device__ __forceinline__ uint4 ldA(const uint32_t* p,int frag,int lane){
    return *(const uint4*)&p[frag*128+lane*4];
}
__device__ __forceinline__ uint2 ldB(const uint32_t* __restrict__ p,int frag,int lane){
    return *(const uint2*)&p[frag*64+lane*2];
}

// ---------------- prep: histogram + weight pre-split/pack --------------------------
__global__ void prep_kernel(const int* __restrict__ dst,const int* __restrict__ ety,
        const float* __restrict__ rW,const float* __restrict__ eW,
        const float* __restrict__ Wi,const float* __restrict__ Wh){
    int i=blockIdx.x*blockDim.x+threadIdx.x;
    if(i<EE) atomicAdd(&g_cnt4[dst[i]*4+ety[i]],1);
    uint32_t hi,lo;
    if(i<8192){                                   // reduce_W [256][64], k-pairs
        int k2=i>>6,n=i&63,k=k2*2;
        split2pack(rW[k*64+n],rW[(k+1)*64+n],hi,lo);
        int off=(k>>6)*2048+bidx16(k&63,n,4);
        g_BredH[off]=hi; g_BredL[off]=lo;
    }else if(i<16384){                            // stacked edge_W
        int q=i-8192; int k2=q>>6,n=q&63,k=k2*2;
        float v0=eW[(k>>6)*4096+(k&63)*64+n];
        float v1=eW[((k+1)>>6)*4096+((k+1)&63)*64+n];
        split2pack(v0,v1,hi,lo);
        int off=(k>>6)*2048+bidx16(k&63,n,4);
        g_BedgeH[off]=hi; g_BedgeL[off]=lo;
    }else if(i<20480){                            // Br K=128
        int q=i-16384; int k2=q>>6,n=q&63,k=k2*2;
        float v0=(k<64)?Wi[n*64+k]:Wh[n*64+k-64];
        float v1=(k+1<64)?Wi[n*64+k+1]:Wh[n*64+k+1-64];
        split2pack(v0,v1,hi,lo);
        int off=bidx16(k,n,8);
        g_BrH[off]=hi; g_BrL[off]=lo;
    }else if(i<24576){                            // Bz K=128
        int q=i-20480; int k2=q>>6,n=q&63,k=k2*2;
        float v0=(k<64)?Wi[(64+n)*64+k]:Wh[(64+n)*64+k-64];
        float v1=(k+1<64)?Wi[(64+n)*64+k+1]:Wh[(64+n)*64+k+1-64];
        split2pack(v0,v1,hi,lo);
        int off=bidx16(k,n,8);
        g_BzH[off]=hi; g_BzL[off]=lo;
    }else if(i<26624){                            // Bin K=64
        int q=i-24576; int k2=q>>6,n=q&63,k=k2*2;
        split2pack(Wi[(128+n)*64+k],Wi[(128+n)*64+k+1],hi,lo);
        int off=bidx16(k,n,4);
        g_BinH[off]=hi; g_BinL[off]=lo;
    }else if(i<28672){                            // Bhn K=64
        int q=i-26624; int k2=q>>6,n=q&63,k=k2*2;
        split2pack(Wh[(128+n)*64+k],Wh[(128+n)*64+k+1],hi,lo);
        int off=bidx16(k,n,4);
        g_BhnH[off]=hi; g_BhnL[off]=lo;
    }
}
__global__ void scan_kernel(){
    __shared__ int part[1024];
    int tid=threadIdx.x; const int CH=(NN+1023)/1024; int base=tid*CH; int s=0;
    for(int i=0;i<CH;++i){ int n=base+i; if(n<NN) s+=g_cnt4[n*4]+g_cnt4[n*4+1]+g_cnt4[n*4+2]+g_cnt4[n*4+3]; }
    part[tid]=s; __syncthreads();
    for(int off=1;off<1024;off<<=1){ int v=(tid>=off)?part[tid-off]:0; __syncthreads(); part[tid]+=v; __syncthreads(); }
    int run=(tid?part[tid-1]:0);
    for(int i=0;i<CH;++i){ int n=base+i; if(n<NN){ g_rowstart[n]=run; g_cursor[n]=run;
        run+=g_cnt4[n*4]+g_cnt4[n*4+1]+g_cnt4[n*4+2]+g_cnt4[n*4+3]; } }
    if(tid==1023) g_rowstart[NN]=part[1023];
}
__global__ void fill_kernel(const int* __restrict__ src,const int* __restrict__ dst,const int* __restrict__ ety){
    int e=blockIdx.x*blockDim.x+threadIdx.x;
    if(e<EE){ int pos=atomicAdd(&g_cursor[dst[e]],1); g_eidx[pos]=(src[e]<<2)|ety[e]; }
}

// ---------------- reduce: h0 = ann @ reduce_W + rb ---------------------------------
// smem u32: Ah [0,4096) Al [4096,8192); 32 KB
#define SMB_R (8192*4)
__global__ __launch_bounds__(256,3) void reduce_mma(const float* __restrict__ ann,
        const float* __restrict__ rb){
    extern __shared__ uint32_t smu[];
    const int tid=threadIdx.x,w=tid>>5,lane=tid&31;
    const int wm=w>>1,wn=w&1,n0=blockIdx.x*128;
    float C[2][4][4]={};
    for(int st=0;st<4;++st){
        if(st>0) __syncthreads();
        for(int idx=tid;idx<2048;idx+=256){
            int row=idx>>4,kq=(idx&15)<<2; int n=n0+row;
            float4 v=make_float4(0,0,0,0);
            if(n<NN) v=*(const float4*)&ann[(size_t)n*256+st*64+kq];
            uint32_t hi,lo;
            split2pack(v.x,v.y,hi,lo);
            int o=aidx16(row,kq,4);   smu[o]=hi; smu[4096+o]=lo;
            split2pack(v.z,v.w,hi,lo);
            o=aidx16(row,kq+2,4);     smu[o]=hi; smu[4096+o]=lo;
        }
        __syncthreads();
        const uint32_t* BH=g_BredH+st*2048;
        const uint32_t* BL=g_BredL+st*2048;
#pragma unroll
        for(int kc=0;kc<4;++kc){
            uint4 ah0=ldA(smu,(wm*2+0)*4+kc,lane);
            uint4 ah1=ldA(smu,(wm*2+1)*4+kc,lane);
            uint4 al0=ldA(smu+4096,(wm*2+0)*4+kc,lane);
            uint4 al1=ldA(smu+4096,(wm*2+1)*4+kc,lane);
            uint2 bh[4],bl[4];
#pragma unroll
            for(int j=0;j<4;++j){
                bh[j]=ldB(BH,(wn*4+j)*4+kc,lane);
                bl[j]=ldB(BL,(wn*4+j)*4+kc,lane);
            }
#pragma unroll
            for(int j=0;j<4;++j){ mma16(C[0][j],(const uint32_t*)&ah0,(const uint32_t*)&bh[j]);
                                  mma16(C[1][j],(const uint32_t*)&ah1,(const uint32_t*)&bh[j]); }
#pragma unroll
            for(int j=0;j<4;++j){ mma16(C[0][j],(const uint32_t*)&ah0,(const uint32_t*)&bl[j]);
                                  mma16(C[1][j],(const uint32_t*)&ah1,(const uint32_t*)&bl[j]); }
#pragma unroll
            for(int j=0;j<4;++j){ mma16(C[0][j],(const uint32_t*)&al0,(const uint32_t*)&bh[j]);
                                  mma16(C[1][j],(const uint32_t*)&al1,(const uint32_t*)&bh[j]); }
        }
    }
    const int g=lane>>2,tig=lane&3;
#pragma unroll
    for(int i=0;i<2;++i){
        int base=n0+(wm*2+i)*16+g;
#pragma unroll
        for(int j=0;j<4;++j){
            int col=(wn*4+j)*8+tig*2;
            float b0=rb[col],b1=rb[col+1];
            if(base<NN){ float2 v={C[i][j][0]+b0,C[i][j][1]+b1};
                *(float2*)&g_h0[(size_t)base*64+col]=v; *(float2*)&g_hA[(size_t)base*64+col]=v; }
            if(base+8<NN){ float2 v={C[i][j][2]+b0,C[i][j][3]+b1};
                *(float2*)&g_h0[(size_t)(base+8)*64+col]=v; *(float2*)&g_hA[(size_t)(base+8)*64+col]=v; }
        }
    }
}

// ---------------- fused step: gather + edge mma + GRU ------------------------------
// smem u32: Ah [0,8192) Al [8192,16384); 64 KB.  gru reuses Ah[0,4096) Al[8192,12288)
#define SMB_S (16384*4)
__global__ __launch_bounds__(256,3) void step_mma(
        const float* __restrict__ hin, float* __restrict__ hout,
        const float* __restrict__ eb, const float* __restrict__ bi,
        const float* __restrict__ bh_){
    extern __shared__ uint32_t smu[];
    const int tid=threadIdx.x,w=tid>>5,lane=tid&31;
    const int wm=w>>1,wn=w&1,n0=blockIdx.x*64;

    // ---- gather (MLP-8, predicated tail) into aggA (kct=16) ----
    for(int i=0;i<8;++i){
        int nloc=w*8+i, n=n0+nloc;
        float2 a0={0,0},a1={0,0},a2={0,0},a3={0,0};
        if(n<NN){
            int e=g_rowstart[n],re=g_rowstart[n+1];
            for(;e<re;e+=8){
                int vv[8]; float2 xx[8];
#pragma unroll
                for(int u=0;u<8;++u){ int idx=(e+u<re)?(e+u):e; vv[u]=g_eidx[idx]; }
#pragma unroll
                for(int u=0;u<8;++u) xx[u]=*(const float2*)&hin[(size_t)(vv[u]>>2)*64+(lane<<1)];
#pragma unroll
                for(int u=0;u<8;++u){
                    if(e+u<re){
                        int t=vv[u]&3;
                        if(t==0){a0.x+=xx[u].x;a0.y+=xx[u].y;}
                        else if(t==1){a1.x+=xx[u].x;a1.y+=xx[u].y;}
                        else if(t==2){a2.x+=xx[u].x;a2.y+=xx[u].y;}
                        else{a3.x+=xx[u].x;a3.y+=xx[u].y;}
                    }
                }
            }
        }
        int k=lane<<1; uint32_t hi,lo; int o;
        split2pack(a0.x,a0.y,hi,lo); o=aidx16(nloc,k,16);     smu[o]=hi; smu[8192+o]=lo;
        split2pack(a1.x,a1.y,hi,lo); o=aidx16(nloc,64+k,16);  smu[o]=hi; smu[8192+o]=lo;
        split2pack(a2.x,a2.y,hi,lo); o=aidx16(nloc,128+k,16); smu[o]=hi; smu[8192+o]=lo;
        split2pack(a3.x,a3.y,hi,lo); o=aidx16(nloc,192+k,16); smu[o]=hi; smu[8192+o]=lo;
    }
    __syncthreads();

    // ---- edge-type mma over 4 stages, barrier-free ----
    float C[4][4]={};
#pragma unroll
    for(int st=0;st<4;++st){
        const uint32_t* BH=g_BedgeH+st*2048;
        const uint32_t* BL=g_BedgeL+st*2048;
#pragma unroll
        for(int kc=0;kc<4;++kc){
            uint4 ah=ldA(smu,wm*16+st*4+kc,lane);
            uint4 al=ldA(smu+8192,wm*16+st*4+kc,lane);
            uint2 bh[4],bl[4];
#pragma unroll
            for(int j=0;j<4;++j){
                bh[j]=ldB(BH,(wn*4+j)*4+kc,lane);
                bl[j]=ldB(BL,(wn*4+j)*4+kc,lane);
            }
#pragma unroll
            for(int j=0;j<4;++j) mma16(C[j],(const uint32_t*)&ah,(const uint32_t*)&bh[j]);
#pragma unroll
            for(int j=0;j<4;++j) mma16(C[j],(const uint32_t*)&ah,(const uint32_t*)&bl[j]);
#pragma unroll
            for(int j=0;j<4;++j) mma16(C[j],(const uint32_t*)&al,(const uint32_t*)&bh[j]);
        }
    }
    __syncthreads();

    // ---- build gruA = [a | h] (kct=8) ----
    const int g=lane>>2,tig=lane&3;
    const int r0loc=wm*16+g, r1loc=r0loc+8;
    const int gr0=n0+r0loc, gr1=n0+r1loc;
    {
        int4 c0=make_int4(0,0,0,0),c1=make_int4(0,0,0,0);
        if(gr0<NN) c0=*(const int4*)&g_cnt4[gr0*4];
        if(gr1<NN) c1=*(const int4*)&g_cnt4[gr1*4];
#pragma unroll
        for(int j=0;j<4;++j){
            int col=(wn*4+j)*8+tig*2;
            float e00=eb[col],e01=eb[col+1],e10=eb[64+col],e11=eb[64+col+1];
            float e20=eb[128+col],e21=eb[128+col+1],e30=eb[192+col],e31=eb[192+col+1];
            float av0=C[j][0]+c0.x*e00+c0.y*e10+c0.z*e20+c0.w*e30;
            float av1=C[j][1]+c0.x*e01+c0.y*e11+c0.z*e21+c0.w*e31;
            float av2=C[j][2]+c1.x*e00+c1.y*e10+c1.z*e20+c1.w*e30;
            float av3=C[j][3]+c1.x*e01+c1.y*e11+c1.z*e21+c1.w*e31;
            uint32_t hi,lo; int o;
            split2pack(av0,av1,hi,lo); o=aidx16(r0loc,col,8); smu[o]=hi; smu[8192+o]=lo;
            split2pack(av2,av3,hi,lo); o=aidx16(r1loc,col,8); smu[o]=hi; smu[8192+o]=lo;
        }
    }
    for(int idx=tid;idx<1024;idx+=256){
        int row=idx>>4,kq=(idx&15)<<2; int n=n0+row;
        float4 v=make_float4(0,0,0,0);
        if(n<NN) v=*(const float4*)&hin[(size_t)n*64+kq];
        uint32_t hi,lo; int o;
        split2pack(v.x,v.y,hi,lo); o=aidx16(row,64+kq,8);   smu[o]=hi; smu[8192+o]=lo;
        split2pack(v.z,v.w,hi,lo); o=aidx16(row,64+kq+2,8); smu[o]=hi; smu[8192+o]=lo;
    }
    __syncthreads();

    // ---- 4 gates, barrier-free ----
    float rv[4][4],tt[4][4],zv[4][4];
#define GATE_MMA(C,BHA,BLA,NKC,AOFF,BKCT)                                 \
    { const uint32_t* BH=(BHA); const uint32_t* BL=(BLA);                 \
      _Pragma("unroll")                                                   \
      for(int kc=0;kc<(NKC);++kc){                                        \
          uint4 ah=ldA(smu,wm*8+(AOFF)+kc,lane);                          \
          uint4 al=ldA(smu+8192,wm*8+(AOFF)+kc,lane);                     \
          uint2 bh[4],bl[4];                                              \
          _Pragma("unroll")                                               \
          for(int j=0;j<4;++j){                                           \
              bh[j]=ldB(BH,(wn*4+j)*(BKCT)+kc,lane);                      \
              bl[j]=ldB(BL,(wn*4+j)*(BKCT)+kc,lane);                      \
          }                                                               \
          _Pragma("unroll")                                               \
          for(int j=0;j<4;++j) mma16(C[j],(const uint32_t*)&ah,(const uint32_t*)&bh[j]); \
          _Pragma("unroll")                                               \
          for(int j=0;j<4;++j) mma16(C[j],(const uint32_t*)&ah,(const uint32_t*)&bl[j]); \
          _Pragma("unroll")                                               \
          for(int j=0;j<4;++j) mma16(C[j],(const uint32_t*)&al,(const uint32_t*)&bh[j]); \
      } }

    { float Cg[4][4]={}; GATE_MMA(Cg,g_BrH,g_BrL,8,0,8)
#pragma unroll
      for(int j=0;j<4;++j)
#pragma unroll
        for(int q=0;q<4;++q){ int col=(wn*4+j)*8+tig*2+(q&1);
            rv[j][q]=1.f/(1.f+expf(-(Cg[j][q]+bi[col]+bh_[col]))); } }
    { float Cg[4][4]={}; GATE_MMA(Cg,g_BhnH,g_BhnL,4,4,4)
#pragma unroll
      for(int j=0;j<4;++j)
#pragma unroll
        for(int q=0;q<4;++q){ int col=(wn*4+j)*8+tig*2+(q&1);
            tt[j][q]=rv[j][q]*(Cg[j][q]+bh_[128+col]); } }
    { float Cg[4][4]={}; GATE_MMA(Cg,g_BzH,g_BzL,8,0,8)
#pragma unroll
      for(int j=0;j<4;++j)
#pragma unroll
        for(int q=0;q<4;++q){ int col=(wn*4+j)*8+tig*2+(q&1);
            zv[j][q]=1.f/(1.f+expf(-(Cg[j][q]+bi[64+col]+bh_[64+col]))); } }
    { float Cg[4][4]={}; GATE_MMA(Cg,g_BinH,g_BinL,4,0,4)
#pragma unroll
      for(int j=0;j<4;++j){
          int col=(wn*4+j)*8+tig*2;
          if(gr0<NN){
              int o=aidx16(r0loc,64+col,8);
              float2 hv=unsplit(smu[o],smu[8192+o]);
              float n0v=tanhf(Cg[j][0]+bi[128+col]+tt[j][0]);
              float n1v=tanhf(Cg[j][1]+bi[128+col+1]+tt[j][1]);
              float2 hn={(1.f-zv[j][0])*n0v+zv[j][0]*hv.x,(1.f-zv[j][1])*n1v+zv[j][1]*hv.y};
              *(float2*)&hout[(size_t)gr0*64+col]=hn;
          }
          if(gr1<NN){
              int o=aidx16(r1loc,64+col,8);
              float2 hv=unsplit(smu[o],smu[8192+o]);
              float n0v=tanhf(Cg[j][2]+bi[128+col]+tt[j][2]);
              float n1v=tanhf(Cg[j][3]+bi[128+col+1]+tt[j][3]);
              float2 hn={(1.f-zv[j][2])*n0v+zv[j][2]*hv.x,(1.f-zv[j][3])*n1v+zv[j][3]*hv.y};
              *(float2*)&hout[(size_t)gr1*64+col]=hn;
          } } }
#undef GATE_MMA
}

// ---------------- attention pooling --------------------------------------------------
__device__ void atomicMaxFloat(float* addr,float v){
    int* ia=(int*)addr; int old=*ia;
    while(true){ float f=__int_as_float(old); if(f>=v) break;
        int as=old; old=atomicCAS(ia,as,__float_as_int(v)); if(old==as) break; }
}
__global__ __launch_bounds__(256) void gate_kernel(const int* __restrict__ gid,
        const float* __restrict__ gW,const float* __restrict__ gb){
    int gt=blockIdx.x*blockDim.x+threadIdx.x; int n=gt>>5; if(n>=NN) return;
    int lane=gt&31,j0=lane<<2;
    float4 fv=(j0<64)?*(const float4*)&g_hA[(size_t)n*64+j0]:*(const float4*)&g_h0[(size_t)n*64+j0-64];
    float4 wv=*(const float4*)&gW[j0];
    float s=fv.x*wv.x+fv.y*wv.y+fv.z*wv.z+fv.w*wv.w;
#pragma unroll
    for(int o=16;o;o>>=1) s+=__shfl_xor_sync(0xffffffffu,s,o);
    if(lane==0){ float g=s+gb[0]; g_gate[n]=g; atomicMaxFloat(&g_gmax[gid[n]],g); }
}
__global__ __launch_bounds__(256) void pool_kernel(const int* __restrict__ gid){
    int gt=blockIdx.x*blockDim.x+threadIdx.x; int n=gt>>5; if(n>=NN) return;
    int lane=gt&31; int g=gid[n];
    float gm=g_gmax[g]; if(!isfinite(gm)) gm=0.f;
    float e=expf(g_gate[n]-gm);
    int j0=lane<<2;
    float4 fv=(j0<64)?*(const float4*)&g_hA[(size_t)n*64+j0]:*(const float4*)&g_h0[(size_t)n*64+j0-64];
    float* rp=&g_rsum[g*128+j0];
    atomicAdd(rp,e*fv.x); atomicAdd(rp+1,e*fv.y); atomicAdd(rp+2,e*fv.z); atomicAdd(rp+3,e*fv.w);
    if(lane==0) atomicAdd(&g_den[g],e);
}
__global__ void out_kernel(const float* __restrict__ oW,const float* __restrict__ ob,float* __restrict__ out){
    int b=blockIdx.x,tid=threadIdx.x;
    float dn=g_den[b]; float inv=(dn>0.f)?(1.f/dn):0.f;
    float r=g_rsum[b*128+tid]*inv;
    float p0=r*oW[tid*2],p1=r*oW[tid*2+1];
#pragma unroll
    for(int o=16;o;o>>=1){ p0+=__shfl_xor_sync(0xffffffffu,p0,o); p1+=__shfl_xor_sync(0xffffffffu,p1,o); }
    __shared__ float s0[4],s1[4];
    if((tid&31)==0){ s0[tid>>5]=p0; s1[tid>>5]=p1; }
    __syncthreads();
    if(tid==0){ out[b*2]=s0[0]+s0[1]+s0[2]+s0[3]+ob[0]; out[b*2+1]=s1[0]+s1[1]+s1[2]+s1[3]+ob[1]; }
}
__global__ void tail_zero(){
    int i=blockIdx.x*blockDim.x+threadIdx.x;
    if(i<NN*4) g_cnt4[i]=0;
    if(i<BB*128) g_rsum[i]=0.f;
    if(i<BB){ g_den[i]=0.f; g_gmax[i]=__int_as_float(0xff800000); }
}

// ---------------- host orchestration --------------------------------------------------
extern "C" void kernel_launch(void* const* d_in,const int* in_sizes,int n_in,
                              void* d_out,int out_size){
    const float* ann=(const float*)d_in[0];
    const int* src=(const int*)d_in[1];
    const int* dst=(const int*)d_in[2];
    const int* ety=(const int*)d_in[3];
    const int* gid=(const int*)d_in[4];
    const float* reduce_W=(const float*)d_in[5];
    const float* reduce_b=(const float*)d_in[6];
    const float* edge_W=(const float*)d_in[7];
    const float* edge_b=(const float*)d_in[8];
    const float* gru_Wi=(const float*)d_in[9];
    const float* gru_bi=(const float*)d_in[10];
    const float* gru_Wh=(const float*)d_in[11];
    const float* gru_bh=(const float*)d_in[12];
    const float* gate_W=(const float*)d_in[13];
    const float* gate_b=(const float*)d_in[14];
    const float* out_W=(const float*)d_in[15];
    const float* out_b=(const float*)d_in[16];
    float* out=(float*)d_out;

    float *hA,*hB;
    cudaGetSymbolAddress((void**)&hA,g_hA);
    cudaGetSymbolAddress((void**)&hB,g_hB);

    cudaFuncSetAttribute(reduce_mma,cudaFuncAttributeMaxDynamicSharedMemorySize,SMB_R);
    cudaFuncSetAttribute(step_mma,cudaFuncAttributeMaxDynamicSharedMemorySize,SMB_S);

    prep_kernel<<<(EE+255)/256,256>>>(dst,ety,reduce_W,edge_W,gru_Wi,gru_Wh);
    scan_kernel<<<1,1024>>>();
    fill_kernel<<<(EE+255)/256,256>>>(src,dst,ety);
    reduce_mma<<<GRID128,256,SMB_R>>>(ann,reduce_b);   // launch #4 -> profiled
    for(int s=0;s<NSTEPS;++s){
        const float* hin=(s&1)?hB:hA;
        float* hout=(s&1)?hA:hB;
        step_mma<<<GRID64,256,SMB_S>>>(hin,hout,edge_b,gru_bi,gru_bh);
    }
    gate_kernel<<<(NN*32+255)/256,256>>>(gid,gate_W,gate_b);
    pool_kernel<<<(NN*32+255)/256,256>>>(gid);
    out_kernel<<<BB,128>>>(out_W,out_b,out);
    tail_zero<<<(NN*4+255)/256,256>>>();
}